// round 11
// baseline (speedup 1.0000x reference)
#include <cuda_runtime.h>
#include <cuda_bf16.h>
#include <math.h>
#include <stdint.h>

// ---------------- problem constants ----------------
#define BB   4
#define NN_  1024
#define DD   768
#define HH   12
#define DH   64
#define HID  2048
#define D3   2304          // 3*D
#define ROWS (BB*NN_)      // 4096
#define ZHN  (BB*HH)       // 48

// ---------------- scratch ----------------
#define OFF_P      0L
#define OFF_XM     49152L
#define OFF_O      3194880L
#define OFF_QKVBF  6340608L
#define OFF_HBF    11059200L
#define OFF_WQ     12632064L
#define OFF_WI     13516800L
#define OFF_WO     15089664L
#define OFF_ACTBF  15876096L
#define SCRATCH_TOTAL 20070400L   // ~80 MB

__device__ float g_scratch[SCRATCH_TOTAL];

// ---------------- PTX helpers ----------------
#define CP_ASYNC16(dst, src) asm volatile("cp.async.cg.shared.global [%0], [%1], 16;\n" :: "r"(dst), "l"(src))
#define CP_COMMIT()  asm volatile("cp.async.commit_group;\n")
#define CP_WAIT1()   asm volatile("cp.async.wait_group 1;\n" ::: "memory")
#define CP_WAIT0()   asm volatile("cp.async.wait_group 0;\n" ::: "memory")

__device__ __forceinline__ void ldsm4(uint32_t& r0, uint32_t& r1, uint32_t& r2, uint32_t& r3, uint32_t addr) {
    asm volatile("ldmatrix.sync.aligned.m8n8.x4.shared.b16 {%0,%1,%2,%3}, [%4];\n"
                 : "=r"(r0), "=r"(r1), "=r"(r2), "=r"(r3) : "r"(addr));
}
__device__ __forceinline__ void ldsm4t(uint32_t& r0, uint32_t& r1, uint32_t& r2, uint32_t& r3, uint32_t addr) {
    asm volatile("ldmatrix.sync.aligned.m8n8.x4.trans.shared.b16 {%0,%1,%2,%3}, [%4];\n"
                 : "=r"(r0), "=r"(r1), "=r"(r2), "=r"(r3) : "r"(addr));
}
__device__ __forceinline__ void mma_bf16(float* c, const uint32_t* a, const uint32_t* b) {
    asm volatile(
        "mma.sync.aligned.m16n8k16.row.col.f32.bf16.bf16.f32 "
        "{%0,%1,%2,%3},{%4,%5,%6,%7},{%8,%9},{%0,%1,%2,%3};\n"
        : "+f"(c[0]), "+f"(c[1]), "+f"(c[2]), "+f"(c[3])
        : "r"(a[0]), "r"(a[1]), "r"(a[2]), "r"(a[3]), "r"(b[0]), "r"(b[1]));
}

// ---------------- fp32 -> bf16 convert ----------------
__global__ void cvt_kernel(const float* __restrict__ in, __nv_bfloat16* __restrict__ out, int n)
{
    int i = (blockIdx.x * 256 + threadIdx.x) * 4;
    if (i >= n) return;
    float4 v = *reinterpret_cast<const float4*>(in + i);
    *reinterpret_cast<__nv_bfloat162*>(out + i)     = __floats2bfloat162_rn(v.x, v.y);
    *reinterpret_cast<__nv_bfloat162*>(out + i + 2) = __floats2bfloat162_rn(v.z, v.w);
}

// ---------------- block reduce ----------------
__device__ __forceinline__ float blk_reduce(float v, float* sm, int op) {
    __syncthreads();
    #pragma unroll
    for (int o = 16; o > 0; o >>= 1) {
        float t = __shfl_xor_sync(0xffffffffu, v, o);
        v = op ? fmaxf(v, t) : (v + t);
    }
    int lane = threadIdx.x & 31, w = threadIdx.x >> 5;
    if (lane == 0) sm[w] = v;
    __syncthreads();
    float r = sm[0];
    #pragma unroll
    for (int i = 1; i < 8; i++) r = op ? fmaxf(r, sm[i]) : (r + sm[i]);
    return r;
}

// ---------------- LayerNorm -> bf16 out ----------------
__global__ __launch_bounds__(256) void ln_kernel(
    const float* __restrict__ x, const float* __restrict__ res,
    const float* __restrict__ g, const float* __restrict__ b,
    __nv_bfloat16* __restrict__ out, float* __restrict__ sum_out)
{
    __shared__ float sm[32];
    long row = blockIdx.x;
    int t = threadIdx.x;
    const float* xr = x + row * DD;
    float v[3];
    float s = 0.f;
    #pragma unroll
    for (int i = 0; i < 3; i++) {
        int idx = t + i * 256;
        float val = xr[idx];
        if (res) val += res[row * DD + idx];
        v[i] = val; s += val;
    }
    float mean = blk_reduce(s, sm, 0) * (1.f / 768.f);
    float vs = 0.f;
    #pragma unroll
    for (int i = 0; i < 3; i++) { float d = v[i] - mean; vs += d * d; }
    float var = blk_reduce(vs, sm, 0) * (1.f / 768.f);
    float rstd = rsqrtf(var + 1e-5f);
    #pragma unroll
    for (int i = 0; i < 3; i++) {
        int idx = t + i * 256;
        if (sum_out) sum_out[row * DD + idx] = v[i];
        out[row * DD + idx] = __float2bfloat16_rn((v[i] - mean) * rstd * g[idx] + b[idx]);
    }
}

// ---------------- p[b,h,n] ----------------
__global__ void p_kernel(const float* __restrict__ coords,
                         const float* __restrict__ rel_w,
                         float* __restrict__ p)
{
    int idx = blockIdx.x * 256 + threadIdx.x;
    if (idx >= ZHN * NN_) return;
    int n = idx & (NN_ - 1);
    int h = (idx >> 10) % HH;
    int b = idx / (HH * NN_);
    const float* c = coords + ((long)b * NN_ + n) * 3;
    const float* w = rel_w + h * 3;
    p[idx] = c[0] * w[0] + c[1] * w[1] + c[2] * w[2];
}

// =====================================================================
// bf16 tensor-core GEMM: C = A(MxK) * B^T + bias [+ res].
// BM=BN=128, BK=64, 8 warps of 64x32, 2 CTAs/SM, dynamic smem (72 KB).
// Smem row stride 72 bf16 (144 B) — conflict-free (same layout as fa).
// =====================================================================
template<bool OBF>
__global__ __launch_bounds__(256, 2) void tgemm(
    const __nv_bfloat16* __restrict__ A, const __nv_bfloat16* __restrict__ B,
    void* __restrict__ Cv,
    int lda, int ldb, int ldc, int K,
    const float* __restrict__ bias, const float* __restrict__ residual)
{
    constexpr int LDSB = 72;                       // bf16 per smem row
    constexpr uint32_t STGB = 128 * LDSB * 2;      // stage bytes per operand
    extern __shared__ __nv_bfloat16 dsm[];         // As[2] | Bs[2]

    const int tid  = threadIdx.x;
    const int lane = tid & 31;
    const int warp = tid >> 5;
    const int wm = warp >> 2;
    const int wn = warp & 3;

    const int row0 = blockIdx.y * 128;
    const int col0 = blockIdx.x * 128;

    const uint32_t asu = (uint32_t)__cvta_generic_to_shared(dsm);
    const uint32_t bsu = asu + 2 * STGB;

    float acc[4][4][4];
    #pragma unroll
    for (int i = 0; i < 4; i++)
        #pragma unroll
        for (int j = 0; j < 4; j++)
            #pragma unroll
            for (int q = 0; q < 4; q++) acc[i][j][q] = 0.f;

    const int KT = K >> 6;

    auto prefetch = [&](int s, int kt) {
        const __nv_bfloat16* Ag = A + (long)row0 * lda + kt * 64;
        const __nv_bfloat16* Bg = B + (long)col0 * ldb + kt * 64;
        #pragma unroll
        for (int i = 0; i < 4; i++) {
            int l = tid + 256 * i;
            int r = l >> 3, c = (l & 7) << 3;
            uint32_t off = (uint32_t)(r * LDSB + c) * 2;
            CP_ASYNC16(asu + s * STGB + off, Ag + (long)r * lda + c);
            CP_ASYNC16(bsu + s * STGB + off, Bg + (long)r * ldb + c);
        }
        CP_COMMIT();
    };

    prefetch(0, 0);

    for (int kt = 0; kt < KT; kt++) {
        if (kt + 1 < KT) { prefetch((kt + 1) & 1, kt + 1); CP_WAIT1(); }
        else             { CP_WAIT0(); }
        __syncthreads();

        const uint32_t ab = asu + (uint32_t)(kt & 1) * STGB;
        const uint32_t bb = bsu + (uint32_t)(kt & 1) * STGB;

        #pragma unroll
        for (int k16 = 0; k16 < 4; k16++) {
            uint32_t af[4][4];
            #pragma unroll
            for (int im = 0; im < 4; im++) {
                int m = wm * 64 + im * 16 + (lane & 15);
                uint32_t addr = ab + (uint32_t)m * (LDSB * 2) + k16 * 32 + ((lane >> 4) & 1) * 16;
                ldsm4(af[im][0], af[im][1], af[im][2], af[im][3], addr);
            }
            #pragma unroll
            for (int ig = 0; ig < 2; ig++) {
                uint32_t bf[4];
                int n = wn * 32 + ig * 16 + (lane & 7) + ((lane >> 4) & 1) * 8;
                uint32_t addr = bb + (uint32_t)n * (LDSB * 2) + k16 * 32 + ((lane >> 3) & 1) * 16;
                ldsm4(bf[0], bf[1], bf[2], bf[3], addr);
                #pragma unroll
                for (int im = 0; im < 4; im++) {
                    mma_bf16(acc[im][ig * 2 + 0], af[im], bf + 0);
                    mma_bf16(acc[im][ig * 2 + 1], af[im], bf + 2);
                }
            }
        }
        __syncthreads();
    }

    #pragma unroll
    for (int im = 0; im < 4; im++) {
        int mrow = row0 + wm * 64 + im * 16 + (lane >> 2);
        #pragma unroll
        for (int jg = 0; jg < 4; jg++) {
            int ncol = col0 + wn * 32 + (jg >> 1) * 16 + (jg & 1) * 8 + 2 * (lane & 3);
            float b0 = 0.f, b1 = 0.f;
            if (bias) { b0 = bias[ncol]; b1 = bias[ncol + 1]; }
            #pragma unroll
            for (int half = 0; half < 2; half++) {
                long r = mrow + half * 8;
                float v0 = acc[im][jg][half * 2 + 0] + b0;
                float v1 = acc[im][jg][half * 2 + 1] + b1;
                if (residual) {
                    v0 += residual[r * ldc + ncol];
                    v1 += residual[r * ldc + ncol + 1];
                }
                if (OBF) {
                    __nv_bfloat16* C = (__nv_bfloat16*)Cv;
                    *reinterpret_cast<__nv_bfloat162*>(&C[r * ldc + ncol]) =
                        __floats2bfloat162_rn(v0, v1);
                } else {
                    float* C = (float*)Cv;
                    float2 vv; vv.x = v0; vv.y = v1;
                    *reinterpret_cast<float2*>(&C[r * ldc + ncol]) = vv;
                }
            }
        }
    }
}
#define TG_SMEM_BYTES (4 * 128 * 72 * 2)   // 73728

// =====================================================================
// Fused FFN-in + SwiGLU (BK=64, stride 72, 2 CTAs/SM, dynamic smem).
// Block: 128 rows x 64 cols of u AND g. act = silu(u)*g -> bf16.
// =====================================================================
__global__ __launch_bounds__(256, 2) void ffn_in_kernel(
    const __nv_bfloat16* __restrict__ A, const __nv_bfloat16* __restrict__ B,
    __nv_bfloat16* __restrict__ act, const float* __restrict__ bias)
{
    constexpr int LDSB = 72;
    constexpr uint32_t ASTG = 128 * LDSB * 2;
    constexpr uint32_t BSTG = 64 * LDSB * 2;
    extern __shared__ __nv_bfloat16 dsm[];   // As[2] | Bu[2] | Bg[2]

    const int tid  = threadIdx.x;
    const int lane = tid & 31;
    const int warp = tid >> 5;
    const int wm = warp >> 2;
    const int wn = warp & 3;

    const int row0 = blockIdx.y * 128;
    const int col0 = blockIdx.x * 64;

    const uint32_t asu = (uint32_t)__cvta_generic_to_shared(dsm);
    const uint32_t buu = asu + 2 * ASTG;
    const uint32_t bgu = buu + 2 * BSTG;

    float accu[4][2][4], accg[4][2][4];
    #pragma unroll
    for (int i = 0; i < 4; i++)
        #pragma unroll
        for (int j = 0; j < 2; j++)
            #pragma unroll
            for (int q = 0; q < 4; q++) { accu[i][j][q] = 0.f; accg[i][j][q] = 0.f; }

    const int KT = DD >> 6;   // 12

    auto prefetch = [&](int s, int kt) {
        const __nv_bfloat16* Ag = A + (long)row0 * DD + kt * 64;
        #pragma unroll
        for (int i = 0; i < 4; i++) {
            int l = tid + 256 * i;
            int r = l >> 3, c = (l & 7) << 3;
            CP_ASYNC16(asu + s * ASTG + (uint32_t)(r * LDSB + c) * 2, Ag + (long)r * DD + c);
        }
        #pragma unroll
        for (int i = 0; i < 2; i++) {
            int l = tid + 256 * i;
            int r = l >> 3, c = (l & 7) << 3;
            uint32_t off = (uint32_t)(r * LDSB + c) * 2;
            CP_ASYNC16(buu + s * BSTG + off, B + (long)(col0 + r) * DD + kt * 64 + c);
            CP_ASYNC16(bgu + s * BSTG + off, B + (long)(HID + col0 + r) * DD + kt * 64 + c);
        }
        CP_COMMIT();
    };

    prefetch(0, 0);

    for (int kt = 0; kt < KT; kt++) {
        if (kt + 1 < KT) { prefetch((kt + 1) & 1, kt + 1); CP_WAIT1(); }
        else             { CP_WAIT0(); }
        __syncthreads();

        const uint32_t ab  = asu + (uint32_t)(kt & 1) * ASTG;
        const uint32_t bub = buu + (uint32_t)(kt & 1) * BSTG;
        const uint32_t bgb = bgu + (uint32_t)(kt & 1) * BSTG;

        #pragma unroll
        for (int k16 = 0; k16 < 4; k16++) {
            uint32_t af[4][4];
            #pragma unroll
            for (int im = 0; im < 4; im++) {
                int m = wm * 64 + im * 16 + (lane & 15);
                uint32_t addr = ab + (uint32_t)m * (LDSB * 2) + k16 * 32 + ((lane >> 4) & 1) * 16;
                ldsm4(af[im][0], af[im][1], af[im][2], af[im][3], addr);
            }
            int n = wn * 16 + (lane & 7) + ((lane >> 4) & 1) * 8;
            uint32_t off = (uint32_t)n * (LDSB * 2) + k16 * 32 + ((lane >> 3) & 1) * 16;
            uint32_t bfu[4], bfg[4];
            ldsm4(bfu[0], bfu[1], bfu[2], bfu[3], bub + off);
            ldsm4(bfg[0], bfg[1], bfg[2], bfg[3], bgb + off);
            #pragma unroll
            for (int im = 0; im < 4; im++) {
                mma_bf16(accu[im][0], af[im], bfu + 0);
                mma_bf16(accu[im][1], af[im], bfu + 2);
                mma_bf16(accg[im][0], af[im], bfg + 0);
                mma_bf16(accg[im][1], af[im], bfg + 2);
            }
        }
        __syncthreads();
    }

    #pragma unroll
    for (int im = 0; im < 4; im++) {
        int mrow = row0 + wm * 64 + im * 16 + (lane >> 2);
        #pragma unroll
        for (int jg = 0; jg < 2; jg++) {
            int col = col0 + wn * 16 + jg * 8 + 2 * (lane & 3);
            float bu0 = bias[col],       bu1 = bias[col + 1];
            float bg0 = bias[HID + col], bg1 = bias[HID + col + 1];
            #pragma unroll
            for (int half = 0; half < 2; half++) {
                long r = mrow + half * 8;
                float u0 = accu[im][jg][half * 2 + 0] + bu0;
                float u1 = accu[im][jg][half * 2 + 1] + bu1;
                float g0 = accg[im][jg][half * 2 + 0] + bg0;
                float g1 = accg[im][jg][half * 2 + 1] + bg1;
                float a0 = u0 / (1.f + __expf(-u0)) * g0;
                float a1 = u1 / (1.f + __expf(-u1)) * g1;
                *reinterpret_cast<__nv_bfloat162*>(&act[r * HID + col]) =
                    __floats2bfloat162_rn(a0, a1);
            }
        }
    }
}
#define FI_SMEM_BYTES ((2 * 128 + 2 * 64 + 2 * 64) * 72 * 2)   // 73728

// =====================================================================
// Fused flash attention, bf16 MMA (unchanged from round 8).
// =====================================================================
struct FaSmem {
    __nv_bfloat16 Qs[128 * 72];
    __nv_bfloat16 Ks[2][64 * 72];
    __nv_bfloat16 Vs[2][64 * 72];
    __nv_bfloat16 Ps[8][16 * 72];
    float psc[2][64];
};
#define FA_SMEM_BYTES (sizeof(FaSmem))

__global__ __launch_bounds__(256, 2) void fa_kernel(
    const __nv_bfloat16* __restrict__ qkv, const float* __restrict__ p,
    float* __restrict__ o)
{
    extern __shared__ float smf[];
    FaSmem* sm = reinterpret_cast<FaSmem*>(smf);
    const int tid = threadIdx.x, lane = tid & 31, warp = tid >> 5;
    const int mt = blockIdx.x;
    const int z  = blockIdx.y;
    const int zb = z / HH, zh = z % HH;

    const __nv_bfloat16* Qg = qkv + ((long)zb * NN_ + mt * 128) * D3 + zh * 64;
    const __nv_bfloat16* Kg = qkv + (long)zb * NN_ * D3 + DD + zh * 64;
    const __nv_bfloat16* Vg = qkv + (long)zb * NN_ * D3 + 2 * DD + zh * 64;
    const float* pg = p + (long)z * NN_;

    const uint32_t qsu  = (uint32_t)__cvta_generic_to_shared(sm->Qs);
    const uint32_t ksu  = (uint32_t)__cvta_generic_to_shared(sm->Ks[0]);
    const uint32_t vsu  = (uint32_t)__cvta_generic_to_shared(sm->Vs[0]);
    const uint32_t psu  = (uint32_t)__cvta_generic_to_shared(sm->Ps[warp]);
    const uint32_t pscu = (uint32_t)__cvta_generic_to_shared(sm->psc[0]);
    constexpr uint32_t KVB = 64 * 72 * 2;

    auto prep = [&](int s, int j) {
        #pragma unroll
        for (int i = 0; i < 2; i++) {
            int l = tid + 256 * i;
            int r = l >> 3, c = (l & 7) << 3;
            CP_ASYNC16(ksu + (uint32_t)s * KVB + (uint32_t)(r * 72 + c) * 2,
                       Kg + (long)(j * 64 + r) * D3 + c);
            CP_ASYNC16(vsu + (uint32_t)s * KVB + (uint32_t)(r * 72 + c) * 2,
                       Vg + (long)(j * 64 + r) * D3 + c);
        }
        if (tid < 16)
            CP_ASYNC16(pscu + (uint32_t)s * 256 + tid * 16, pg + j * 64 + tid * 4);
        CP_COMMIT();
    };

    #pragma unroll
    for (int i = 0; i < 4; i++) {
        int l = tid + 256 * i;
        int r = l >> 3, c = (l & 7) << 3;
        CP_ASYNC16(qsu + (uint32_t)(r * 72 + c) * 2, Qg + (long)r * D3 + c);
    }
    prep(0, 0);

    float m0 = -1e30f, m1 = -1e30f, l0 = 0.f, l1 = 0.f;
    float oacc[4][2][4];
    #pragma unroll
    for (int a = 0; a < 4; a++)
        #pragma unroll
        for (int b = 0; b < 2; b++)
            #pragma unroll
            for (int q = 0; q < 4; q++) oacc[a][b][q] = 0.f;

    for (int j = 0; j < 16; j++) {
        const int s = j & 1;
        __syncthreads();
        if (j < 15) { prep(s ^ 1, j + 1); CP_WAIT1(); }
        else        { CP_WAIT0(); }
        __syncthreads();

        float sacc[4][2][4];
        #pragma unroll
        for (int a = 0; a < 4; a++)
            #pragma unroll
            for (int b = 0; b < 2; b++)
                #pragma unroll
                for (int q = 0; q < 4; q++) sacc[a][b][q] = 0.f;

        const uint32_t ksb = ksu + (uint32_t)s * KVB;
        #pragma unroll
        for (int k16 = 0; k16 < 4; k16++) {
            uint32_t af[4];
            {
                int m = warp * 16 + (lane & 15);
                uint32_t addr = qsu + (uint32_t)m * 144 + k16 * 32 + ((lane >> 4) & 1) * 16;
                ldsm4(af[0], af[1], af[2], af[3], addr);
            }
            #pragma unroll
            for (int ig = 0; ig < 4; ig++) {
                uint32_t bf[4];
                int n = ig * 16 + (lane & 7) + ((lane >> 4) & 1) * 8;
                uint32_t addr = ksb + (uint32_t)n * 144 + k16 * 32 + ((lane >> 3) & 1) * 16;
                ldsm4(bf[0], bf[1], bf[2], bf[3], addr);
                mma_bf16(sacc[ig][0], af, bf + 0);
                mma_bf16(sacc[ig][1], af, bf + 2);
            }
        }

        #pragma unroll
        for (int ig = 0; ig < 4; ig++)
            #pragma unroll
            for (int hf = 0; hf < 2; hf++) {
                int cb = ig * 16 + hf * 8 + 2 * (lane & 3);
                float p0 = sm->psc[s][cb], p1 = sm->psc[s][cb + 1];
                sacc[ig][hf][0] = sacc[ig][hf][0] * 0.125f - p0;
                sacc[ig][hf][1] = sacc[ig][hf][1] * 0.125f - p1;
                sacc[ig][hf][2] = sacc[ig][hf][2] * 0.125f - p0;
                sacc[ig][hf][3] = sacc[ig][hf][3] * 0.125f - p1;
            }

        float mx0 = -1e30f, mx1 = -1e30f;
        #pragma unroll
        for (int ig = 0; ig < 4; ig++)
            #pragma unroll
            for (int hf = 0; hf < 2; hf++) {
                mx0 = fmaxf(mx0, fmaxf(sacc[ig][hf][0], sacc[ig][hf][1]));
                mx1 = fmaxf(mx1, fmaxf(sacc[ig][hf][2], sacc[ig][hf][3]));
            }
        #pragma unroll
        for (int off = 1; off <= 2; off <<= 1) {
            mx0 = fmaxf(mx0, __shfl_xor_sync(0xffffffffu, mx0, off));
            mx1 = fmaxf(mx1, __shfl_xor_sync(0xffffffffu, mx1, off));
        }
        float mn0 = fmaxf(m0, mx0), mn1 = fmaxf(m1, mx1);
        float f0 = __expf(m0 - mn0), f1 = __expf(m1 - mn1);
        float s0 = 0.f, s1 = 0.f;
        #pragma unroll
        for (int ig = 0; ig < 4; ig++)
            #pragma unroll
            for (int hf = 0; hf < 2; hf++) {
                sacc[ig][hf][0] = __expf(sacc[ig][hf][0] - mn0);
                sacc[ig][hf][1] = __expf(sacc[ig][hf][1] - mn0);
                sacc[ig][hf][2] = __expf(sacc[ig][hf][2] - mn1);
                sacc[ig][hf][3] = __expf(sacc[ig][hf][3] - mn1);
                s0 += sacc[ig][hf][0] + sacc[ig][hf][1];
                s1 += sacc[ig][hf][2] + sacc[ig][hf][3];
            }
        #pragma unroll
        for (int off = 1; off <= 2; off <<= 1) {
            s0 += __shfl_xor_sync(0xffffffffu, s0, off);
            s1 += __shfl_xor_sync(0xffffffffu, s1, off);
        }
        l0 = l0 * f0 + s0;  l1 = l1 * f1 + s1;
        m0 = mn0;           m1 = mn1;
        #pragma unroll
        for (int ig = 0; ig < 4; ig++)
            #pragma unroll
            for (int hf = 0; hf < 2; hf++) {
                oacc[ig][hf][0] *= f0; oacc[ig][hf][1] *= f0;
                oacc[ig][hf][2] *= f1; oacc[ig][hf][3] *= f1;
            }

        {
            __nv_bfloat16* psw = sm->Ps[warp];
            int r0 = lane >> 2;
            #pragma unroll
            for (int ig = 0; ig < 4; ig++)
                #pragma unroll
                for (int hf = 0; hf < 2; hf++) {
                    int cb = ig * 16 + hf * 8 + 2 * (lane & 3);
                    *reinterpret_cast<__nv_bfloat162*>(&psw[r0 * 72 + cb]) =
                        __floats2bfloat162_rn(sacc[ig][hf][0], sacc[ig][hf][1]);
                    *reinterpret_cast<__nv_bfloat162*>(&psw[(r0 + 8) * 72 + cb]) =
                        __floats2bfloat162_rn(sacc[ig][hf][2], sacc[ig][hf][3]);
                }
        }
        __syncwarp();

        const uint32_t vsb = vsu + (uint32_t)s * KVB;
        #pragma unroll
        for (int k16 = 0; k16 < 4; k16++) {
            uint32_t af[4];
            {
                int m = lane & 15;
                uint32_t addr = psu + (uint32_t)m * 144 + k16 * 32 + ((lane >> 4) & 1) * 16;
                ldsm4(af[0], af[1], af[2], af[3], addr);
            }
            #pragma unroll
            for (int ig = 0; ig < 4; ig++) {
                uint32_t bf[4];
                int key = k16 * 16 + ((lane >> 3) & 1) * 8 + (lane & 7);
                uint32_t addr = vsb + (uint32_t)key * 144 + ig * 32 + ((lane >> 4) & 1) * 16;
                ldsm4t(bf[0], bf[1], bf[2], bf[3], addr);
                mma_bf16(oacc[ig][0], af, bf + 0);
                mma_bf16(oacc[ig][1], af, bf + 2);
            }
        }
    }

    float inv0 = 1.f / l0, inv1 = 1.f / l1;
    long gi = (long)zb * NN_ + mt * 128 + warp * 16 + (lane >> 2);
    #pragma unroll
    for (int ig = 0; ig < 4; ig++)
        #pragma unroll
        for (int hf = 0; hf < 2; hf++) {
            int c = zh * 64 + ig * 16 + hf * 8 + 2 * (lane & 3);
            float2 a; a.x = oacc[ig][hf][0] * inv0; a.y = oacc[ig][hf][1] * inv0;
            float2 b; b.x = oacc[ig][hf][2] * inv1; b.y = oacc[ig][hf][3] * inv1;
            *reinterpret_cast<float2*>(&o[gi * DD + c]) = a;
            *reinterpret_cast<float2*>(&o[(gi + 8) * DD + c]) = b;
        }
}

// ---------------- launch ----------------
extern "C" void kernel_launch(void* const* d_in, const int* in_sizes, int n_in,
                              void* d_out, int out_size)
{
    const float* x      = (const float*)d_in[0];
    const float* coords = (const float*)d_in[1];
    const float* ln1_g  = (const float*)d_in[2];
    const float* ln1_b  = (const float*)d_in[3];
    const float* qkv_w  = (const float*)d_in[4];
    const float* qkv_b  = (const float*)d_in[5];
    const float* rel_w  = (const float*)d_in[6];
    const float* ln2_g  = (const float*)d_in[7];
    const float* ln2_b  = (const float*)d_in[8];
    const float* win_w  = (const float*)d_in[9];
    const float* win_b  = (const float*)d_in[10];
    const float* wout_w = (const float*)d_in[11];
    const float* wout_b = (const float*)d_in[12];
    float* out = (float*)d_out;

    float* S = nullptr;
    cudaGetSymbolAddress((void**)&S, g_scratch);
    float* p   = S + OFF_P;
    float* xm  = S + OFF_XM;
    float* o   = S + OFF_O;
    __nv_bfloat16* qkvbf = (__nv_bfloat16*)(S + OFF_QKVBF);
    __nv_bfloat16* hbf   = (__nv_bfloat16*)(S + OFF_HBF);
    __nv_bfloat16* wqbf  = (__nv_bfloat16*)(S + OFF_WQ);
    __nv_bfloat16* wibf  = (__nv_bfloat16*)(S + OFF_WI);
    __nv_bfloat16* wobf  = (__nv_bfloat16*)(S + OFF_WO);
    __nv_bfloat16* actbf = (__nv_bfloat16*)(S + OFF_ACTBF);

    cudaFuncSetAttribute(fa_kernel, cudaFuncAttributeMaxDynamicSharedMemorySize,
                         (int)FA_SMEM_BYTES);
    cudaFuncSetAttribute(tgemm<true>,  cudaFuncAttributeMaxDynamicSharedMemorySize, TG_SMEM_BYTES);
    cudaFuncSetAttribute(tgemm<false>, cudaFuncAttributeMaxDynamicSharedMemorySize, TG_SMEM_BYTES);
    cudaFuncSetAttribute(ffn_in_kernel, cudaFuncAttributeMaxDynamicSharedMemorySize, FI_SMEM_BYTES);

    // 0) weight converts
    cvt_kernel<<<(D3*DD)/1024, 256>>>(qkv_w, wqbf, D3*DD);
    cvt_kernel<<<(2*HID*DD)/1024, 256>>>(win_w, wibf, 2*HID*DD);
    cvt_kernel<<<(DD*HID)/1024, 256>>>(wout_w, wobf, DD*HID);

    // 1) h = LN1(x) -> bf16
    ln_kernel<<<ROWS, 256>>>(x, nullptr, ln1_g, ln1_b, hbf, nullptr);

    // 2) qkv = h @ qkv_w^T + qkv_b -> bf16
    tgemm<true><<<dim3(D3/128, ROWS/128), 256, TG_SMEM_BYTES>>>(
        hbf, wqbf, qkvbf, DD, DD, D3, DD, qkv_b, nullptr);

    // 3) p[b,h,n]
    p_kernel<<<(ZHN*NN_)/256, 256>>>(coords, rel_w, p);

    // 4-6) fused attention -> o (fp32)
    fa_kernel<<<dim3(8, ZHN), 256, FA_SMEM_BYTES>>>(qkvbf, p, o);

    // 7) xm = x + o ; h2 = LN2(xm) -> bf16
    ln_kernel<<<ROWS, 256>>>(x, o, ln2_g, ln2_b, hbf, xm);

    // 8+9) act = silu(h2 Wu^T + bu) * (h2 Wg^T + bg) -> bf16 (fused)
    ffn_in_kernel<<<dim3(HID/64, ROWS/128), 256, FI_SMEM_BYTES>>>(hbf, wibf, actbf, win_b);

    // 10) out = act @ wout_w^T + wout_b + xm -> fp32
    tgemm<false><<<dim3(DD/128, ROWS/128), 256, TG_SMEM_BYTES>>>(
        actbf, wobf, out, HID, HID, DD, HID, wout_b, xm);
}

// round 12
// speedup vs baseline: 1.5513x; 1.5513x over previous
#include <cuda_runtime.h>
#include <cuda_bf16.h>
#include <math.h>
#include <stdint.h>

// ---------------- problem constants ----------------
#define BB   4
#define NN_  1024
#define DD   768
#define HH   12
#define DH   64
#define HID  2048
#define D3   2304          // 3*D
#define ROWS (BB*NN_)      // 4096
#define ZHN  (BB*HH)       // 48

// ---------------- scratch ----------------
#define OFF_P      0L
#define OFF_XM     49152L
#define OFF_O      3194880L
#define OFF_QKVBF  6340608L
#define OFF_HBF    11059200L
#define OFF_WQ     12632064L
#define OFF_WI     13516800L
#define OFF_WO     15089664L
#define OFF_ACTBF  15876096L
#define SCRATCH_TOTAL 20070400L   // ~80 MB

__device__ float g_scratch[SCRATCH_TOTAL];

// ---------------- PTX helpers ----------------
#define CP_ASYNC16(dst, src) asm volatile("cp.async.cg.shared.global [%0], [%1], 16;\n" :: "r"(dst), "l"(src))
#define CP_COMMIT()  asm volatile("cp.async.commit_group;\n")
#define CP_WAIT1()   asm volatile("cp.async.wait_group 1;\n" ::: "memory")
#define CP_WAIT0()   asm volatile("cp.async.wait_group 0;\n" ::: "memory")

__device__ __forceinline__ void ldsm4(uint32_t& r0, uint32_t& r1, uint32_t& r2, uint32_t& r3, uint32_t addr) {
    asm volatile("ldmatrix.sync.aligned.m8n8.x4.shared.b16 {%0,%1,%2,%3}, [%4];\n"
                 : "=r"(r0), "=r"(r1), "=r"(r2), "=r"(r3) : "r"(addr));
}
__device__ __forceinline__ void ldsm4t(uint32_t& r0, uint32_t& r1, uint32_t& r2, uint32_t& r3, uint32_t addr) {
    asm volatile("ldmatrix.sync.aligned.m8n8.x4.trans.shared.b16 {%0,%1,%2,%3}, [%4];\n"
                 : "=r"(r0), "=r"(r1), "=r"(r2), "=r"(r3) : "r"(addr));
}
__device__ __forceinline__ void mma_bf16(float* c, const uint32_t* a, const uint32_t* b) {
    asm volatile(
        "mma.sync.aligned.m16n8k16.row.col.f32.bf16.bf16.f32 "
        "{%0,%1,%2,%3},{%4,%5,%6,%7},{%8,%9},{%0,%1,%2,%3};\n"
        : "+f"(c[0]), "+f"(c[1]), "+f"(c[2]), "+f"(c[3])
        : "r"(a[0]), "r"(a[1]), "r"(a[2]), "r"(a[3]), "r"(b[0]), "r"(b[1]));
}

// ---------------- fp32 -> bf16 convert (all three weights, one launch) ----------------
// Destinations are contiguous in scratch: [WQ | WI | WO].
#define N_WQ (D3*DD)        // 1769472
#define N_WI (2*HID*DD)     // 3145728
#define N_WO (DD*HID)       // 1572864
#define N_CVT (N_WQ + N_WI + N_WO)   // 6488064

__global__ void cvt3_kernel(const float* __restrict__ wq, const float* __restrict__ wi,
                            const float* __restrict__ wo, __nv_bfloat16* __restrict__ out)
{
    long i = ((long)blockIdx.x * 256 + threadIdx.x) * 4;
    if (i >= N_CVT) return;
    const float* src;
    long j = i;
    if (j < N_WQ)                 { src = wq; }
    else if (j < N_WQ + N_WI)     { src = wi; j -= N_WQ; }
    else                          { src = wo; j -= (long)N_WQ + N_WI; }
    float4 v = *reinterpret_cast<const float4*>(src + j);
    *reinterpret_cast<__nv_bfloat162*>(out + i)     = __floats2bfloat162_rn(v.x, v.y);
    *reinterpret_cast<__nv_bfloat162*>(out + i + 2) = __floats2bfloat162_rn(v.z, v.w);
}

// ---------------- block reduce ----------------
__device__ __forceinline__ float blk_reduce(float v, float* sm, int op) {
    __syncthreads();
    #pragma unroll
    for (int o = 16; o > 0; o >>= 1) {
        float t = __shfl_xor_sync(0xffffffffu, v, o);
        v = op ? fmaxf(v, t) : (v + t);
    }
    int lane = threadIdx.x & 31, w = threadIdx.x >> 5;
    if (lane == 0) sm[w] = v;
    __syncthreads();
    float r = sm[0];
    #pragma unroll
    for (int i = 1; i < 8; i++) r = op ? fmaxf(r, sm[i]) : (r + sm[i]);
    return r;
}

// ---------------- LayerNorm -> bf16 out ----------------
__global__ __launch_bounds__(256) void ln_kernel(
    const float* __restrict__ x, const float* __restrict__ res,
    const float* __restrict__ g, const float* __restrict__ b,
    __nv_bfloat16* __restrict__ out, float* __restrict__ sum_out)
{
    __shared__ float sm[32];
    long row = blockIdx.x;
    int t = threadIdx.x;
    const float* xr = x + row * DD;
    float v[3];
    float s = 0.f;
    #pragma unroll
    for (int i = 0; i < 3; i++) {
        int idx = t + i * 256;
        float val = xr[idx];
        if (res) val += res[row * DD + idx];
        v[i] = val; s += val;
    }
    float mean = blk_reduce(s, sm, 0) * (1.f / 768.f);
    float vs = 0.f;
    #pragma unroll
    for (int i = 0; i < 3; i++) { float d = v[i] - mean; vs += d * d; }
    float var = blk_reduce(vs, sm, 0) * (1.f / 768.f);
    float rstd = rsqrtf(var + 1e-5f);
    #pragma unroll
    for (int i = 0; i < 3; i++) {
        int idx = t + i * 256;
        if (sum_out) sum_out[row * DD + idx] = v[i];
        out[row * DD + idx] = __float2bfloat16_rn((v[i] - mean) * rstd * g[idx] + b[idx]);
    }
}

// ---------------- p[b,h,n] ----------------
__global__ void p_kernel(const float* __restrict__ coords,
                         const float* __restrict__ rel_w,
                         float* __restrict__ p)
{
    int idx = blockIdx.x * 256 + threadIdx.x;
    if (idx >= ZHN * NN_) return;
    int n = idx & (NN_ - 1);
    int h = (idx >> 10) % HH;
    int b = idx / (HH * NN_);
    const float* c = coords + ((long)b * NN_ + n) * 3;
    const float* w = rel_w + h * 3;
    p[idx] = c[0] * w[0] + c[1] * w[1] + c[2] * w[2];
}

// =====================================================================
// bf16 tensor-core GEMM: C = A(MxK) * B^T + bias [+ res].
// BM=BN=128, BK=64, 8 warps of 64x32, 2 CTAs/SM, dynamic smem (72 KB).
// =====================================================================
template<bool OBF>
__global__ __launch_bounds__(256, 2) void tgemm(
    const __nv_bfloat16* __restrict__ A, const __nv_bfloat16* __restrict__ B,
    void* __restrict__ Cv,
    int lda, int ldb, int ldc, int K,
    const float* __restrict__ bias, const float* __restrict__ residual)
{
    constexpr int LDSB = 72;                       // bf16 per smem row
    constexpr uint32_t STGB = 128 * LDSB * 2;      // stage bytes per operand
    extern __shared__ __nv_bfloat16 dsm[];         // As[2] | Bs[2]

    const int tid  = threadIdx.x;
    const int lane = tid & 31;
    const int warp = tid >> 5;
    const int wm = warp >> 2;
    const int wn = warp & 3;

    const int row0 = blockIdx.y * 128;
    const int col0 = blockIdx.x * 128;

    const uint32_t asu = (uint32_t)__cvta_generic_to_shared(dsm);
    const uint32_t bsu = asu + 2 * STGB;

    float acc[4][4][4];
    #pragma unroll
    for (int i = 0; i < 4; i++)
        #pragma unroll
        for (int j = 0; j < 4; j++)
            #pragma unroll
            for (int q = 0; q < 4; q++) acc[i][j][q] = 0.f;

    const int KT = K >> 6;

    auto prefetch = [&](int s, int kt) {
        const __nv_bfloat16* Ag = A + (long)row0 * lda + kt * 64;
        const __nv_bfloat16* Bg = B + (long)col0 * ldb + kt * 64;
        #pragma unroll
        for (int i = 0; i < 4; i++) {
            int l = tid + 256 * i;
            int r = l >> 3, c = (l & 7) << 3;
            uint32_t off = (uint32_t)(r * LDSB + c) * 2;
            CP_ASYNC16(asu + s * STGB + off, Ag + (long)r * lda + c);
            CP_ASYNC16(bsu + s * STGB + off, Bg + (long)r * ldb + c);
        }
        CP_COMMIT();
    };

    prefetch(0, 0);

    for (int kt = 0; kt < KT; kt++) {
        if (kt + 1 < KT) { prefetch((kt + 1) & 1, kt + 1); CP_WAIT1(); }
        else             { CP_WAIT0(); }
        __syncthreads();

        const uint32_t ab = asu + (uint32_t)(kt & 1) * STGB;
        const uint32_t bb = bsu + (uint32_t)(kt & 1) * STGB;

        #pragma unroll
        for (int k16 = 0; k16 < 4; k16++) {
            uint32_t af[4][4];
            #pragma unroll
            for (int im = 0; im < 4; im++) {
                int m = wm * 64 + im * 16 + (lane & 15);
                uint32_t addr = ab + (uint32_t)m * (LDSB * 2) + k16 * 32 + ((lane >> 4) & 1) * 16;
                ldsm4(af[im][0], af[im][1], af[im][2], af[im][3], addr);
            }
            #pragma unroll
            for (int ig = 0; ig < 2; ig++) {
                uint32_t bf[4];
                int n = wn * 32 + ig * 16 + (lane & 7) + ((lane >> 4) & 1) * 8;
                uint32_t addr = bb + (uint32_t)n * (LDSB * 2) + k16 * 32 + ((lane >> 3) & 1) * 16;
                ldsm4(bf[0], bf[1], bf[2], bf[3], addr);
                #pragma unroll
                for (int im = 0; im < 4; im++) {
                    mma_bf16(acc[im][ig * 2 + 0], af[im], bf + 0);
                    mma_bf16(acc[im][ig * 2 + 1], af[im], bf + 2);
                }
            }
        }
        __syncthreads();
    }

    #pragma unroll
    for (int im = 0; im < 4; im++) {
        int mrow = row0 + wm * 64 + im * 16 + (lane >> 2);
        #pragma unroll
        for (int jg = 0; jg < 4; jg++) {
            int ncol = col0 + wn * 32 + (jg >> 1) * 16 + (jg & 1) * 8 + 2 * (lane & 3);
            float b0 = 0.f, b1 = 0.f;
            if (bias) { b0 = bias[ncol]; b1 = bias[ncol + 1]; }
            #pragma unroll
            for (int half = 0; half < 2; half++) {
                long r = mrow + half * 8;
                float v0 = acc[im][jg][half * 2 + 0] + b0;
                float v1 = acc[im][jg][half * 2 + 1] + b1;
                if (residual) {
                    v0 += residual[r * ldc + ncol];
                    v1 += residual[r * ldc + ncol + 1];
                }
                if (OBF) {
                    __nv_bfloat16* C = (__nv_bfloat16*)Cv;
                    *reinterpret_cast<__nv_bfloat162*>(&C[r * ldc + ncol]) =
                        __floats2bfloat162_rn(v0, v1);
                } else {
                    float* C = (float*)Cv;
                    float2 vv; vv.x = v0; vv.y = v1;
                    *reinterpret_cast<float2*>(&C[r * ldc + ncol]) = vv;
                }
            }
        }
    }
}
#define TG_SMEM_BYTES (4 * 128 * 72 * 2)   // 73728

// =====================================================================
// Fused FFN-in + SwiGLU (BK=64, stride 72, 2 CTAs/SM, dynamic smem).
// =====================================================================
__global__ __launch_bounds__(256, 2) void ffn_in_kernel(
    const __nv_bfloat16* __restrict__ A, const __nv_bfloat16* __restrict__ B,
    __nv_bfloat16* __restrict__ act, const float* __restrict__ bias)
{
    constexpr int LDSB = 72;
    constexpr uint32_t ASTG = 128 * LDSB * 2;
    constexpr uint32_t BSTG = 64 * LDSB * 2;
    extern __shared__ __nv_bfloat16 dsm[];   // As[2] | Bu[2] | Bg[2]

    const int tid  = threadIdx.x;
    const int lane = tid & 31;
    const int warp = tid >> 5;
    const int wm = warp >> 2;
    const int wn = warp & 3;

    const int row0 = blockIdx.y * 128;
    const int col0 = blockIdx.x * 64;

    const uint32_t asu = (uint32_t)__cvta_generic_to_shared(dsm);
    const uint32_t buu = asu + 2 * ASTG;
    const uint32_t bgu = buu + 2 * BSTG;

    float accu[4][2][4], accg[4][2][4];
    #pragma unroll
    for (int i = 0; i < 4; i++)
        #pragma unroll
        for (int j = 0; j < 2; j++)
            #pragma unroll
            for (int q = 0; q < 4; q++) { accu[i][j][q] = 0.f; accg[i][j][q] = 0.f; }

    const int KT = DD >> 6;   // 12

    auto prefetch = [&](int s, int kt) {
        const __nv_bfloat16* Ag = A + (long)row0 * DD + kt * 64;
        #pragma unroll
        for (int i = 0; i < 4; i++) {
            int l = tid + 256 * i;
            int r = l >> 3, c = (l & 7) << 3;
            CP_ASYNC16(asu + s * ASTG + (uint32_t)(r * LDSB + c) * 2, Ag + (long)r * DD + c);
        }
        #pragma unroll
        for (int i = 0; i < 2; i++) {
            int l = tid + 256 * i;
            int r = l >> 3, c = (l & 7) << 3;
            uint32_t off = (uint32_t)(r * LDSB + c) * 2;
            CP_ASYNC16(buu + s * BSTG + off, B + (long)(col0 + r) * DD + kt * 64 + c);
            CP_ASYNC16(bgu + s * BSTG + off, B + (long)(HID + col0 + r) * DD + kt * 64 + c);
        }
        CP_COMMIT();
    };

    prefetch(0, 0);

    for (int kt = 0; kt < KT; kt++) {
        if (kt + 1 < KT) { prefetch((kt + 1) & 1, kt + 1); CP_WAIT1(); }
        else             { CP_WAIT0(); }
        __syncthreads();

        const uint32_t ab  = asu + (uint32_t)(kt & 1) * ASTG;
        const uint32_t bub = buu + (uint32_t)(kt & 1) * BSTG;
        const uint32_t bgb = bgu + (uint32_t)(kt & 1) * BSTG;

        #pragma unroll
        for (int k16 = 0; k16 < 4; k16++) {
            uint32_t af[4][4];
            #pragma unroll
            for (int im = 0; im < 4; im++) {
                int m = wm * 64 + im * 16 + (lane & 15);
                uint32_t addr = ab + (uint32_t)m * (LDSB * 2) + k16 * 32 + ((lane >> 4) & 1) * 16;
                ldsm4(af[im][0], af[im][1], af[im][2], af[im][3], addr);
            }
            int n = wn * 16 + (lane & 7) + ((lane >> 4) & 1) * 8;
            uint32_t off = (uint32_t)n * (LDSB * 2) + k16 * 32 + ((lane >> 3) & 1) * 16;
            uint32_t bfu[4], bfg[4];
            ldsm4(bfu[0], bfu[1], bfu[2], bfu[3], bub + off);
            ldsm4(bfg[0], bfg[1], bfg[2], bfg[3], bgb + off);
            #pragma unroll
            for (int im = 0; im < 4; im++) {
                mma_bf16(accu[im][0], af[im], bfu + 0);
                mma_bf16(accu[im][1], af[im], bfu + 2);
                mma_bf16(accg[im][0], af[im], bfg + 0);
                mma_bf16(accg[im][1], af[im], bfg + 2);
            }
        }
        __syncthreads();
    }

    #pragma unroll
    for (int im = 0; im < 4; im++) {
        int mrow = row0 + wm * 64 + im * 16 + (lane >> 2);
        #pragma unroll
        for (int jg = 0; jg < 2; jg++) {
            int col = col0 + wn * 16 + jg * 8 + 2 * (lane & 3);
            float bu0 = bias[col],       bu1 = bias[col + 1];
            float bg0 = bias[HID + col], bg1 = bias[HID + col + 1];
            #pragma unroll
            for (int half = 0; half < 2; half++) {
                long r = mrow + half * 8;
                float u0 = accu[im][jg][half * 2 + 0] + bu0;
                float u1 = accu[im][jg][half * 2 + 1] + bu1;
                float g0 = accg[im][jg][half * 2 + 0] + bg0;
                float g1 = accg[im][jg][half * 2 + 1] + bg1;
                float a0 = u0 / (1.f + __expf(-u0)) * g0;
                float a1 = u1 / (1.f + __expf(-u1)) * g1;
                *reinterpret_cast<__nv_bfloat162*>(&act[r * HID + col]) =
                    __floats2bfloat162_rn(a0, a1);
            }
        }
    }
}
#define FI_SMEM_BYTES ((2 * 128 + 2 * 64 + 2 * 64) * 72 * 2)   // 73728

// =====================================================================
// Fused flash attention, bf16 MMA (unchanged since round 7).
// =====================================================================
struct FaSmem {
    __nv_bfloat16 Qs[128 * 72];
    __nv_bfloat16 Ks[2][64 * 72];
    __nv_bfloat16 Vs[2][64 * 72];
    __nv_bfloat16 Ps[8][16 * 72];
    float psc[2][64];
};
#define FA_SMEM_BYTES (sizeof(FaSmem))

__global__ __launch_bounds__(256, 2) void fa_kernel(
    const __nv_bfloat16* __restrict__ qkv, const float* __restrict__ p,
    float* __restrict__ o)
{
    extern __shared__ float smf[];
    FaSmem* sm = reinterpret_cast<FaSmem*>(smf);
    const int tid = threadIdx.x, lane = tid & 31, warp = tid >> 5;
    const int mt = blockIdx.x;
    const int z  = blockIdx.y;
    const int zb = z / HH, zh = z % HH;

    const __nv_bfloat16* Qg = qkv + ((long)zb * NN_ + mt * 128) * D3 + zh * 64;
    const __nv_bfloat16* Kg = qkv + (long)zb * NN_ * D3 + DD + zh * 64;
    const __nv_bfloat16* Vg = qkv + (long)zb * NN_ * D3 + 2 * DD + zh * 64;
    const float* pg = p + (long)z * NN_;

    const uint32_t qsu  = (uint32_t)__cvta_generic_to_shared(sm->Qs);
    const uint32_t ksu  = (uint32_t)__cvta_generic_to_shared(sm->Ks[0]);
    const uint32_t vsu  = (uint32_t)__cvta_generic_to_shared(sm->Vs[0]);
    const uint32_t psu  = (uint32_t)__cvta_generic_to_shared(sm->Ps[warp]);
    const uint32_t pscu = (uint32_t)__cvta_generic_to_shared(sm->psc[0]);
    constexpr uint32_t KVB = 64 * 72 * 2;

    auto prep = [&](int s, int j) {
        #pragma unroll
        for (int i = 0; i < 2; i++) {
            int l = tid + 256 * i;
            int r = l >> 3, c = (l & 7) << 3;
            CP_ASYNC16(ksu + (uint32_t)s * KVB + (uint32_t)(r * 72 + c) * 2,
                       Kg + (long)(j * 64 + r) * D3 + c);
            CP_ASYNC16(vsu + (uint32_t)s * KVB + (uint32_t)(r * 72 + c) * 2,
                       Vg + (long)(j * 64 + r) * D3 + c);
        }
        if (tid < 16)
            CP_ASYNC16(pscu + (uint32_t)s * 256 + tid * 16, pg + j * 64 + tid * 4);
        CP_COMMIT();
    };

    #pragma unroll
    for (int i = 0; i < 4; i++) {
        int l = tid + 256 * i;
        int r = l >> 3, c = (l & 7) << 3;
        CP_ASYNC16(qsu + (uint32_t)(r * 72 + c) * 2, Qg + (long)r * D3 + c);
    }
    prep(0, 0);

    float m0 = -1e30f, m1 = -1e30f, l0 = 0.f, l1 = 0.f;
    float oacc[4][2][4];
    #pragma unroll
    for (int a = 0; a < 4; a++)
        #pragma unroll
        for (int b = 0; b < 2; b++)
            #pragma unroll
            for (int q = 0; q < 4; q++) oacc[a][b][q] = 0.f;

    for (int j = 0; j < 16; j++) {
        const int s = j & 1;
        __syncthreads();
        if (j < 15) { prep(s ^ 1, j + 1); CP_WAIT1(); }
        else        { CP_WAIT0(); }
        __syncthreads();

        float sacc[4][2][4];
        #pragma unroll
        for (int a = 0; a < 4; a++)
            #pragma unroll
            for (int b = 0; b < 2; b++)
                #pragma unroll
                for (int q = 0; q < 4; q++) sacc[a][b][q] = 0.f;

        const uint32_t ksb = ksu + (uint32_t)s * KVB;
        #pragma unroll
        for (int k16 = 0; k16 < 4; k16++) {
            uint32_t af[4];
            {
                int m = warp * 16 + (lane & 15);
                uint32_t addr = qsu + (uint32_t)m * 144 + k16 * 32 + ((lane >> 4) & 1) * 16;
                ldsm4(af[0], af[1], af[2], af[3], addr);
            }
            #pragma unroll
            for (int ig = 0; ig < 4; ig++) {
                uint32_t bf[4];
                int n = ig * 16 + (lane & 7) + ((lane >> 4) & 1) * 8;
                uint32_t addr = ksb + (uint32_t)n * 144 + k16 * 32 + ((lane >> 3) & 1) * 16;
                ldsm4(bf[0], bf[1], bf[2], bf[3], addr);
                mma_bf16(sacc[ig][0], af, bf + 0);
                mma_bf16(sacc[ig][1], af, bf + 2);
            }
        }

        #pragma unroll
        for (int ig = 0; ig < 4; ig++)
            #pragma unroll
            for (int hf = 0; hf < 2; hf++) {
                int cb = ig * 16 + hf * 8 + 2 * (lane & 3);
                float p0 = sm->psc[s][cb], p1 = sm->psc[s][cb + 1];
                sacc[ig][hf][0] = sacc[ig][hf][0] * 0.125f - p0;
                sacc[ig][hf][1] = sacc[ig][hf][1] * 0.125f - p1;
                sacc[ig][hf][2] = sacc[ig][hf][2] * 0.125f - p0;
                sacc[ig][hf][3] = sacc[ig][hf][3] * 0.125f - p1;
            }

        float mx0 = -1e30f, mx1 = -1e30f;
        #pragma unroll
        for (int ig = 0; ig < 4; ig++)
            #pragma unroll
            for (int hf = 0; hf < 2; hf++) {
                mx0 = fmaxf(mx0, fmaxf(sacc[ig][hf][0], sacc[ig][hf][1]));
                mx1 = fmaxf(mx1, fmaxf(sacc[ig][hf][2], sacc[ig][hf][3]));
            }
        #pragma unroll
        for (int off = 1; off <= 2; off <<= 1) {
            mx0 = fmaxf(mx0, __shfl_xor_sync(0xffffffffu, mx0, off));
            mx1 = fmaxf(mx1, __shfl_xor_sync(0xffffffffu, mx1, off));
        }
        float mn0 = fmaxf(m0, mx0), mn1 = fmaxf(m1, mx1);
        float f0 = __expf(m0 - mn0), f1 = __expf(m1 - mn1);
        float s0 = 0.f, s1 = 0.f;
        #pragma unroll
        for (int ig = 0; ig < 4; ig++)
            #pragma unroll
            for (int hf = 0; hf < 2; hf++) {
                sacc[ig][hf][0] = __expf(sacc[ig][hf][0] - mn0);
                sacc[ig][hf][1] = __expf(sacc[ig][hf][1] - mn0);
                sacc[ig][hf][2] = __expf(sacc[ig][hf][2] - mn1);
                sacc[ig][hf][3] = __expf(sacc[ig][hf][3] - mn1);
                s0 += sacc[ig][hf][0] + sacc[ig][hf][1];
                s1 += sacc[ig][hf][2] + sacc[ig][hf][3];
            }
        #pragma unroll
        for (int off = 1; off <= 2; off <<= 1) {
            s0 += __shfl_xor_sync(0xffffffffu, s0, off);
            s1 += __shfl_xor_sync(0xffffffffu, s1, off);
        }
        l0 = l0 * f0 + s0;  l1 = l1 * f1 + s1;
        m0 = mn0;           m1 = mn1;
        #pragma unroll
        for (int ig = 0; ig < 4; ig++)
            #pragma unroll
            for (int hf = 0; hf < 2; hf++) {
                oacc[ig][hf][0] *= f0; oacc[ig][hf][1] *= f0;
                oacc[ig][hf][2] *= f1; oacc[ig][hf][3] *= f1;
            }

        {
            __nv_bfloat16* psw = sm->Ps[warp];
            int r0 = lane >> 2;
            #pragma unroll
            for (int ig = 0; ig < 4; ig++)
                #pragma unroll
                for (int hf = 0; hf < 2; hf++) {
                    int cb = ig * 16 + hf * 8 + 2 * (lane & 3);
                    *reinterpret_cast<__nv_bfloat162*>(&psw[r0 * 72 + cb]) =
                        __floats2bfloat162_rn(sacc[ig][hf][0], sacc[ig][hf][1]);
                    *reinterpret_cast<__nv_bfloat162*>(&psw[(r0 + 8) * 72 + cb]) =
                        __floats2bfloat162_rn(sacc[ig][hf][2], sacc[ig][hf][3]);
                }
        }
        __syncwarp();

        const uint32_t vsb = vsu + (uint32_t)s * KVB;
        #pragma unroll
        for (int k16 = 0; k16 < 4; k16++) {
            uint32_t af[4];
            {
                int m = lane & 15;
                uint32_t addr = psu + (uint32_t)m * 144 + k16 * 32 + ((lane >> 4) & 1) * 16;
                ldsm4(af[0], af[1], af[2], af[3], addr);
            }
            #pragma unroll
            for (int ig = 0; ig < 4; ig++) {
                uint32_t bf[4];
                int key = k16 * 16 + ((lane >> 3) & 1) * 8 + (lane & 7);
                uint32_t addr = vsb + (uint32_t)key * 144 + ig * 32 + ((lane >> 4) & 1) * 16;
                ldsm4t(bf[0], bf[1], bf[2], bf[3], addr);
                mma_bf16(oacc[ig][0], af, bf + 0);
                mma_bf16(oacc[ig][1], af, bf + 2);
            }
        }
    }

    float inv0 = 1.f / l0, inv1 = 1.f / l1;
    long gi = (long)zb * NN_ + mt * 128 + warp * 16 + (lane >> 2);
    #pragma unroll
    for (int ig = 0; ig < 4; ig++)
        #pragma unroll
        for (int hf = 0; hf < 2; hf++) {
            int c = zh * 64 + ig * 16 + hf * 8 + 2 * (lane & 3);
            float2 a; a.x = oacc[ig][hf][0] * inv0; a.y = oacc[ig][hf][1] * inv0;
            float2 b; b.x = oacc[ig][hf][2] * inv1; b.y = oacc[ig][hf][3] * inv1;
            *reinterpret_cast<float2*>(&o[gi * DD + c]) = a;
            *reinterpret_cast<float2*>(&o[(gi + 8) * DD + c]) = b;
        }
}

// ---------------- launch ----------------
extern "C" void kernel_launch(void* const* d_in, const int* in_sizes, int n_in,
                              void* d_out, int out_size)
{
    const float* x      = (const float*)d_in[0];
    const float* coords = (const float*)d_in[1];
    const float* ln1_g  = (const float*)d_in[2];
    const float* ln1_b  = (const float*)d_in[3];
    const float* qkv_w  = (const float*)d_in[4];
    const float* qkv_b  = (const float*)d_in[5];
    const float* rel_w  = (const float*)d_in[6];
    const float* ln2_g  = (const float*)d_in[7];
    const float* ln2_b  = (const float*)d_in[8];
    const float* win_w  = (const float*)d_in[9];
    const float* win_b  = (const float*)d_in[10];
    const float* wout_w = (const float*)d_in[11];
    const float* wout_b = (const float*)d_in[12];
    float* out = (float*)d_out;

    float* S = nullptr;
    cudaGetSymbolAddress((void**)&S, g_scratch);
    float* p   = S + OFF_P;
    float* xm  = S + OFF_XM;
    float* o   = S + OFF_O;
    __nv_bfloat16* qkvbf = (__nv_bfloat16*)(S + OFF_QKVBF);
    __nv_bfloat16* hbf   = (__nv_bfloat16*)(S + OFF_HBF);
    __nv_bfloat16* wqbf  = (__nv_bfloat16*)(S + OFF_WQ);
    __nv_bfloat16* wibf  = (__nv_bfloat16*)(S + OFF_WI);
    __nv_bfloat16* wobf  = (__nv_bfloat16*)(S + OFF_WO);
    __nv_bfloat16* actbf = (__nv_bfloat16*)(S + OFF_ACTBF);

    cudaFuncSetAttribute(fa_kernel, cudaFuncAttributeMaxDynamicSharedMemorySize,
                         (int)FA_SMEM_BYTES);
    cudaFuncSetAttribute(tgemm<true>,  cudaFuncAttributeMaxDynamicSharedMemorySize, TG_SMEM_BYTES);
    cudaFuncSetAttribute(tgemm<false>, cudaFuncAttributeMaxDynamicSharedMemorySize, TG_SMEM_BYTES);
    cudaFuncSetAttribute(ffn_in_kernel, cudaFuncAttributeMaxDynamicSharedMemorySize, FI_SMEM_BYTES);

    // 0) all three weight converts in one launch (dests contiguous: WQ|WI|WO)
    cvt3_kernel<<<(N_CVT/4 + 255)/256, 256>>>(qkv_w, win_w, wout_w, wqbf);

    // 1) h = LN1(x) -> bf16
    ln_kernel<<<ROWS, 256>>>(x, nullptr, ln1_g, ln1_b, hbf, nullptr);

    // 2) qkv = h @ qkv_w^T + qkv_b -> bf16
    tgemm<true><<<dim3(D3/128, ROWS/128), 256, TG_SMEM_BYTES>>>(
        hbf, wqbf, qkvbf, DD, DD, D3, DD, qkv_b, nullptr);

    // 3) p[b,h,n]
    p_kernel<<<(ZHN*NN_)/256, 256>>>(coords, rel_w, p);

    // 4-6) fused attention -> o (fp32)
    fa_kernel<<<dim3(8, ZHN), 256, FA_SMEM_BYTES>>>(qkvbf, p, o);

    // 7) xm = x + o ; h2 = LN2(xm) -> bf16
    ln_kernel<<<ROWS, 256>>>(x, o, ln2_g, ln2_b, hbf, xm);

    // 8+9) act = silu(h2 Wu^T + bu) * (h2 Wg^T + bg) -> bf16 (fused)
    ffn_in_kernel<<<dim3(HID/64, ROWS/128), 256, FI_SMEM_BYTES>>>(hbf, wibf, actbf, win_b);

    // 10) out = act @ wout_w^T + wout_b + xm -> fp32
    tgemm<false><<<dim3(DD/128, ROWS/128), 256, TG_SMEM_BYTES>>>(
        actbf, wobf, out, HID, HID, DD, HID, wout_b, xm);
}

// round 13
// speedup vs baseline: 1.5756x; 1.0156x over previous
#include <cuda_runtime.h>
#include <cuda_bf16.h>
#include <math.h>
#include <stdint.h>

// ---------------- problem constants ----------------
#define BB   4
#define NN_  1024
#define DD   768
#define HH   12
#define DH   64
#define HID  2048
#define D3   2304          // 3*D
#define ROWS (BB*NN_)      // 4096
#define ZHN  (BB*HH)       // 48

// ---------------- scratch ----------------
#define OFF_P      0L
#define OFF_XM     49152L
#define OFF_O      3194880L
#define OFF_QKVBF  6340608L
#define OFF_HBF    11059200L
#define OFF_WQ     12632064L
#define OFF_WI     13516800L
#define OFF_WO     15089664L
#define OFF_ACTBF  15876096L
#define SCRATCH_TOTAL 20070400L   // ~80 MB

__device__ float g_scratch[SCRATCH_TOTAL];

// ---------------- PTX helpers ----------------
#define CP_ASYNC16(dst, src) asm volatile("cp.async.cg.shared.global [%0], [%1], 16;\n" :: "r"(dst), "l"(src))
#define CP_COMMIT()  asm volatile("cp.async.commit_group;\n")
#define CP_WAIT1()   asm volatile("cp.async.wait_group 1;\n" ::: "memory")
#define CP_WAIT0()   asm volatile("cp.async.wait_group 0;\n" ::: "memory")

__device__ __forceinline__ void ldsm4(uint32_t& r0, uint32_t& r1, uint32_t& r2, uint32_t& r3, uint32_t addr) {
    asm volatile("ldmatrix.sync.aligned.m8n8.x4.shared.b16 {%0,%1,%2,%3}, [%4];\n"
                 : "=r"(r0), "=r"(r1), "=r"(r2), "=r"(r3) : "r"(addr));
}
__device__ __forceinline__ void ldsm4t(uint32_t& r0, uint32_t& r1, uint32_t& r2, uint32_t& r3, uint32_t addr) {
    asm volatile("ldmatrix.sync.aligned.m8n8.x4.trans.shared.b16 {%0,%1,%2,%3}, [%4];\n"
                 : "=r"(r0), "=r"(r1), "=r"(r2), "=r"(r3) : "r"(addr));
}
__device__ __forceinline__ void mma_bf16(float* c, const uint32_t* a, const uint32_t* b) {
    asm volatile(
        "mma.sync.aligned.m16n8k16.row.col.f32.bf16.bf16.f32 "
        "{%0,%1,%2,%3},{%4,%5,%6,%7},{%8,%9},{%0,%1,%2,%3};\n"
        : "+f"(c[0]), "+f"(c[1]), "+f"(c[2]), "+f"(c[3])
        : "r"(a[0]), "r"(a[1]), "r"(a[2]), "r"(a[3]), "r"(b[0]), "r"(b[1]));
}

// ---------------- fp32 -> bf16 convert (3 weights) + p bias, one launch ----------------
// Destinations contiguous in scratch: [WQ | WI | WO]. Tail thread-range computes p.
#define N_WQ (D3*DD)        // 1769472
#define N_WI (2*HID*DD)     // 3145728
#define N_WO (DD*HID)       // 1572864
#define N_CVT (N_WQ + N_WI + N_WO)   // 6488064
#define CVT_THREADS (N_CVT/4)        // 1622016 (multiple of 256)

__global__ void cvt3p_kernel(const float* __restrict__ wq, const float* __restrict__ wi,
                             const float* __restrict__ wo, __nv_bfloat16* __restrict__ out,
                             const float* __restrict__ coords, const float* __restrict__ rel_w,
                             float* __restrict__ p)
{
    long gt = (long)blockIdx.x * 256 + threadIdx.x;
    if (gt < CVT_THREADS) {
        long i = gt * 4;
        const float* src;
        long j = i;
        if (j < N_WQ)             { src = wq; }
        else if (j < N_WQ + N_WI) { src = wi; j -= N_WQ; }
        else                      { src = wo; j -= (long)N_WQ + N_WI; }
        float4 v = *reinterpret_cast<const float4*>(src + j);
        *reinterpret_cast<__nv_bfloat162*>(out + i)     = __floats2bfloat162_rn(v.x, v.y);
        *reinterpret_cast<__nv_bfloat162*>(out + i + 2) = __floats2bfloat162_rn(v.z, v.w);
    } else {
        int idx = (int)(gt - CVT_THREADS);
        if (idx >= ZHN * NN_) return;
        int n = idx & (NN_ - 1);
        int h = (idx >> 10) % HH;
        int b = idx / (HH * NN_);
        const float* c = coords + ((long)b * NN_ + n) * 3;
        const float* w = rel_w + h * 3;
        p[idx] = c[0] * w[0] + c[1] * w[1] + c[2] * w[2];
    }
}

// ---------------- block reduce ----------------
__device__ __forceinline__ float blk_reduce(float v, float* sm, int op) {
    __syncthreads();
    #pragma unroll
    for (int o = 16; o > 0; o >>= 1) {
        float t = __shfl_xor_sync(0xffffffffu, v, o);
        v = op ? fmaxf(v, t) : (v + t);
    }
    int lane = threadIdx.x & 31, w = threadIdx.x >> 5;
    if (lane == 0) sm[w] = v;
    __syncthreads();
    float r = sm[0];
    #pragma unroll
    for (int i = 1; i < 8; i++) r = op ? fmaxf(r, sm[i]) : (r + sm[i]);
    return r;
}

// ---------------- LayerNorm -> bf16 out ----------------
__global__ __launch_bounds__(256) void ln_kernel(
    const float* __restrict__ x, const float* __restrict__ res,
    const float* __restrict__ g, const float* __restrict__ b,
    __nv_bfloat16* __restrict__ out, float* __restrict__ sum_out)
{
    __shared__ float sm[32];
    long row = blockIdx.x;
    int t = threadIdx.x;
    const float* xr = x + row * DD;
    float v[3];
    float s = 0.f;
    #pragma unroll
    for (int i = 0; i < 3; i++) {
        int idx = t + i * 256;
        float val = xr[idx];
        if (res) val += res[row * DD + idx];
        v[i] = val; s += val;
    }
    float mean = blk_reduce(s, sm, 0) * (1.f / 768.f);
    float vs = 0.f;
    #pragma unroll
    for (int i = 0; i < 3; i++) { float d = v[i] - mean; vs += d * d; }
    float var = blk_reduce(vs, sm, 0) * (1.f / 768.f);
    float rstd = rsqrtf(var + 1e-5f);
    #pragma unroll
    for (int i = 0; i < 3; i++) {
        int idx = t + i * 256;
        if (sum_out) sum_out[row * DD + idx] = v[i];
        out[row * DD + idx] = __float2bfloat16_rn((v[i] - mean) * rstd * g[idx] + b[idx]);
    }
}

// =====================================================================
// bf16 tensor-core GEMM: C = A(MxK) * B^T + bias [+ res].
// BMt x 128 tile, BK=64, 8 warps of (BMt/2)x32, 2 CTAs/SM, dynamic smem.
// Smem row stride 72 bf16 (144 B) — conflict-free ldmatrix.
// =====================================================================
template<bool OBF, int BMt>
__global__ __launch_bounds__(256, 2) void tgemm(
    const __nv_bfloat16* __restrict__ A, const __nv_bfloat16* __restrict__ B,
    void* __restrict__ Cv,
    int lda, int ldb, int ldc, int K,
    const float* __restrict__ bias, const float* __restrict__ residual)
{
    constexpr int LDSB = 72;                       // bf16 per smem row
    constexpr int WMR  = BMt / 2;                  // rows per wm group
    constexpr int MF   = WMR / 16;                 // 16-row frags per warp
    constexpr int AITER = BMt / 32;                // prefetch iters for A
    constexpr uint32_t ASTG = BMt * LDSB * 2;
    constexpr uint32_t BSTG = 128 * LDSB * 2;
    extern __shared__ __nv_bfloat16 dsm[];         // As[2] | Bs[2]

    const int tid  = threadIdx.x;
    const int lane = tid & 31;
    const int warp = tid >> 5;
    const int wm = warp >> 2;
    const int wn = warp & 3;

    const int row0 = blockIdx.y * BMt;
    const int col0 = blockIdx.x * 128;

    const uint32_t asu = (uint32_t)__cvta_generic_to_shared(dsm);
    const uint32_t bsu = asu + 2 * ASTG;

    float acc[MF][4][4];
    #pragma unroll
    for (int i = 0; i < MF; i++)
        #pragma unroll
        for (int j = 0; j < 4; j++)
            #pragma unroll
            for (int q = 0; q < 4; q++) acc[i][j][q] = 0.f;

    const int KT = K >> 6;

    auto prefetch = [&](int s, int kt) {
        const __nv_bfloat16* Ag = A + (long)row0 * lda + kt * 64;
        const __nv_bfloat16* Bg = B + (long)col0 * ldb + kt * 64;
        #pragma unroll
        for (int i = 0; i < AITER; i++) {
            int l = tid + 256 * i;
            int r = l >> 3, c = (l & 7) << 3;
            CP_ASYNC16(asu + s * ASTG + (uint32_t)(r * LDSB + c) * 2, Ag + (long)r * lda + c);
        }
        #pragma unroll
        for (int i = 0; i < 4; i++) {
            int l = tid + 256 * i;
            int r = l >> 3, c = (l & 7) << 3;
            CP_ASYNC16(bsu + s * BSTG + (uint32_t)(r * LDSB + c) * 2, Bg + (long)r * ldb + c);
        }
        CP_COMMIT();
    };

    prefetch(0, 0);

    for (int kt = 0; kt < KT; kt++) {
        if (kt + 1 < KT) { prefetch((kt + 1) & 1, kt + 1); CP_WAIT1(); }
        else             { CP_WAIT0(); }
        __syncthreads();

        const uint32_t ab = asu + (uint32_t)(kt & 1) * ASTG;
        const uint32_t bb = bsu + (uint32_t)(kt & 1) * BSTG;

        #pragma unroll
        for (int k16 = 0; k16 < 4; k16++) {
            uint32_t af[MF][4];
            #pragma unroll
            for (int im = 0; im < MF; im++) {
                int m = wm * WMR + im * 16 + (lane & 15);
                uint32_t addr = ab + (uint32_t)m * (LDSB * 2) + k16 * 32 + ((lane >> 4) & 1) * 16;
                ldsm4(af[im][0], af[im][1], af[im][2], af[im][3], addr);
            }
            #pragma unroll
            for (int ig = 0; ig < 2; ig++) {
                uint32_t bf[4];
                int n = wn * 32 + ig * 16 + (lane & 7) + ((lane >> 4) & 1) * 8;
                uint32_t addr = bb + (uint32_t)n * (LDSB * 2) + k16 * 32 + ((lane >> 3) & 1) * 16;
                ldsm4(bf[0], bf[1], bf[2], bf[3], addr);
                #pragma unroll
                for (int im = 0; im < MF; im++) {
                    mma_bf16(acc[im][ig * 2 + 0], af[im], bf + 0);
                    mma_bf16(acc[im][ig * 2 + 1], af[im], bf + 2);
                }
            }
        }
        __syncthreads();
    }

    #pragma unroll
    for (int im = 0; im < MF; im++) {
        int mrow = row0 + wm * WMR + im * 16 + (lane >> 2);
        #pragma unroll
        for (int jg = 0; jg < 4; jg++) {
            int ncol = col0 + wn * 32 + (jg >> 1) * 16 + (jg & 1) * 8 + 2 * (lane & 3);
            float b0 = 0.f, b1 = 0.f;
            if (bias) { b0 = bias[ncol]; b1 = bias[ncol + 1]; }
            #pragma unroll
            for (int half = 0; half < 2; half++) {
                long r = mrow + half * 8;
                float v0 = acc[im][jg][half * 2 + 0] + b0;
                float v1 = acc[im][jg][half * 2 + 1] + b1;
                if (residual) {
                    v0 += residual[r * ldc + ncol];
                    v1 += residual[r * ldc + ncol + 1];
                }
                if (OBF) {
                    __nv_bfloat16* C = (__nv_bfloat16*)Cv;
                    *reinterpret_cast<__nv_bfloat162*>(&C[r * ldc + ncol]) =
                        __floats2bfloat162_rn(v0, v1);
                } else {
                    float* C = (float*)Cv;
                    float2 vv; vv.x = v0; vv.y = v1;
                    *reinterpret_cast<float2*>(&C[r * ldc + ncol]) = vv;
                }
            }
        }
    }
}
#define TG_SMEM_BYTES(BM_)  ((2 * (BM_) + 2 * 128) * 72 * 2)

// =====================================================================
// Fused FFN-in + SwiGLU (BK=64, stride 72, 2 CTAs/SM, dynamic smem).
// =====================================================================
__global__ __launch_bounds__(256, 2) void ffn_in_kernel(
    const __nv_bfloat16* __restrict__ A, const __nv_bfloat16* __restrict__ B,
    __nv_bfloat16* __restrict__ act, const float* __restrict__ bias)
{
    constexpr int LDSB = 72;
    constexpr uint32_t ASTG = 128 * LDSB * 2;
    constexpr uint32_t BSTG = 64 * LDSB * 2;
    extern __shared__ __nv_bfloat16 dsm[];   // As[2] | Bu[2] | Bg[2]

    const int tid  = threadIdx.x;
    const int lane = tid & 31;
    const int warp = tid >> 5;
    const int wm = warp >> 2;
    const int wn = warp & 3;

    const int row0 = blockIdx.y * 128;
    const int col0 = blockIdx.x * 64;

    const uint32_t asu = (uint32_t)__cvta_generic_to_shared(dsm);
    const uint32_t buu = asu + 2 * ASTG;
    const uint32_t bgu = buu + 2 * BSTG;

    float accu[4][2][4], accg[4][2][4];
    #pragma unroll
    for (int i = 0; i < 4; i++)
        #pragma unroll
        for (int j = 0; j < 2; j++)
            #pragma unroll
            for (int q = 0; q < 4; q++) { accu[i][j][q] = 0.f; accg[i][j][q] = 0.f; }

    const int KT = DD >> 6;   // 12

    auto prefetch = [&](int s, int kt) {
        const __nv_bfloat16* Ag = A + (long)row0 * DD + kt * 64;
        #pragma unroll
        for (int i = 0; i < 4; i++) {
            int l = tid + 256 * i;
            int r = l >> 3, c = (l & 7) << 3;
            CP_ASYNC16(asu + s * ASTG + (uint32_t)(r * LDSB + c) * 2, Ag + (long)r * DD + c);
        }
        #pragma unroll
        for (int i = 0; i < 2; i++) {
            int l = tid + 256 * i;
            int r = l >> 3, c = (l & 7) << 3;
            uint32_t off = (uint32_t)(r * LDSB + c) * 2;
            CP_ASYNC16(buu + s * BSTG + off, B + (long)(col0 + r) * DD + kt * 64 + c);
            CP_ASYNC16(bgu + s * BSTG + off, B + (long)(HID + col0 + r) * DD + kt * 64 + c);
        }
        CP_COMMIT();
    };

    prefetch(0, 0);

    for (int kt = 0; kt < KT; kt++) {
        if (kt + 1 < KT) { prefetch((kt + 1) & 1, kt + 1); CP_WAIT1(); }
        else             { CP_WAIT0(); }
        __syncthreads();

        const uint32_t ab  = asu + (uint32_t)(kt & 1) * ASTG;
        const uint32_t bub = buu + (uint32_t)(kt & 1) * BSTG;
        const uint32_t bgb = bgu + (uint32_t)(kt & 1) * BSTG;

        #pragma unroll
        for (int k16 = 0; k16 < 4; k16++) {
            uint32_t af[4][4];
            #pragma unroll
            for (int im = 0; im < 4; im++) {
                int m = wm * 64 + im * 16 + (lane & 15);
                uint32_t addr = ab + (uint32_t)m * (LDSB * 2) + k16 * 32 + ((lane >> 4) & 1) * 16;
                ldsm4(af[im][0], af[im][1], af[im][2], af[im][3], addr);
            }
            int n = wn * 16 + (lane & 7) + ((lane >> 4) & 1) * 8;
            uint32_t off = (uint32_t)n * (LDSB * 2) + k16 * 32 + ((lane >> 3) & 1) * 16;
            uint32_t bfu[4], bfg[4];
            ldsm4(bfu[0], bfu[1], bfu[2], bfu[3], bub + off);
            ldsm4(bfg[0], bfg[1], bfg[2], bfg[3], bgb + off);
            #pragma unroll
            for (int im = 0; im < 4; im++) {
                mma_bf16(accu[im][0], af[im], bfu + 0);
                mma_bf16(accu[im][1], af[im], bfu + 2);
                mma_bf16(accg[im][0], af[im], bfg + 0);
                mma_bf16(accg[im][1], af[im], bfg + 2);
            }
        }
        __syncthreads();
    }

    #pragma unroll
    for (int im = 0; im < 4; im++) {
        int mrow = row0 + wm * 64 + im * 16 + (lane >> 2);
        #pragma unroll
        for (int jg = 0; jg < 2; jg++) {
            int col = col0 + wn * 16 + jg * 8 + 2 * (lane & 3);
            float bu0 = bias[col],       bu1 = bias[col + 1];
            float bg0 = bias[HID + col], bg1 = bias[HID + col + 1];
            #pragma unroll
            for (int half = 0; half < 2; half++) {
                long r = mrow + half * 8;
                float u0 = accu[im][jg][half * 2 + 0] + bu0;
                float u1 = accu[im][jg][half * 2 + 1] + bu1;
                float g0 = accg[im][jg][half * 2 + 0] + bg0;
                float g1 = accg[im][jg][half * 2 + 1] + bg1;
                float a0 = u0 / (1.f + __expf(-u0)) * g0;
                float a1 = u1 / (1.f + __expf(-u1)) * g1;
                *reinterpret_cast<__nv_bfloat162*>(&act[r * HID + col]) =
                    __floats2bfloat162_rn(a0, a1);
            }
        }
    }
}
#define FI_SMEM_BYTES ((2 * 128 + 2 * 64 + 2 * 64) * 72 * 2)   // 73728

// =====================================================================
// Fused flash attention, bf16 MMA (unchanged since round 7).
// =====================================================================
struct FaSmem {
    __nv_bfloat16 Qs[128 * 72];
    __nv_bfloat16 Ks[2][64 * 72];
    __nv_bfloat16 Vs[2][64 * 72];
    __nv_bfloat16 Ps[8][16 * 72];
    float psc[2][64];
};
#define FA_SMEM_BYTES (sizeof(FaSmem))

__global__ __launch_bounds__(256, 2) void fa_kernel(
    const __nv_bfloat16* __restrict__ qkv, const float* __restrict__ p,
    float* __restrict__ o)
{
    extern __shared__ float smf[];
    FaSmem* sm = reinterpret_cast<FaSmem*>(smf);
    const int tid = threadIdx.x, lane = tid & 31, warp = tid >> 5;
    const int mt = blockIdx.x;
    const int z  = blockIdx.y;
    const int zb = z / HH, zh = z % HH;

    const __nv_bfloat16* Qg = qkv + ((long)zb * NN_ + mt * 128) * D3 + zh * 64;
    const __nv_bfloat16* Kg = qkv + (long)zb * NN_ * D3 + DD + zh * 64;
    const __nv_bfloat16* Vg = qkv + (long)zb * NN_ * D3 + 2 * DD + zh * 64;
    const float* pg = p + (long)z * NN_;

    const uint32_t qsu  = (uint32_t)__cvta_generic_to_shared(sm->Qs);
    const uint32_t ksu  = (uint32_t)__cvta_generic_to_shared(sm->Ks[0]);
    const uint32_t vsu  = (uint32_t)__cvta_generic_to_shared(sm->Vs[0]);
    const uint32_t psu  = (uint32_t)__cvta_generic_to_shared(sm->Ps[warp]);
    const uint32_t pscu = (uint32_t)__cvta_generic_to_shared(sm->psc[0]);
    constexpr uint32_t KVB = 64 * 72 * 2;

    auto prep = [&](int s, int j) {
        #pragma unroll
        for (int i = 0; i < 2; i++) {
            int l = tid + 256 * i;
            int r = l >> 3, c = (l & 7) << 3;
            CP_ASYNC16(ksu + (uint32_t)s * KVB + (uint32_t)(r * 72 + c) * 2,
                       Kg + (long)(j * 64 + r) * D3 + c);
            CP_ASYNC16(vsu + (uint32_t)s * KVB + (uint32_t)(r * 72 + c) * 2,
                       Vg + (long)(j * 64 + r) * D3 + c);
        }
        if (tid < 16)
            CP_ASYNC16(pscu + (uint32_t)s * 256 + tid * 16, pg + j * 64 + tid * 4);
        CP_COMMIT();
    };

    #pragma unroll
    for (int i = 0; i < 4; i++) {
        int l = tid + 256 * i;
        int r = l >> 3, c = (l & 7) << 3;
        CP_ASYNC16(qsu + (uint32_t)(r * 72 + c) * 2, Qg + (long)r * D3 + c);
    }
    prep(0, 0);

    float m0 = -1e30f, m1 = -1e30f, l0 = 0.f, l1 = 0.f;
    float oacc[4][2][4];
    #pragma unroll
    for (int a = 0; a < 4; a++)
        #pragma unroll
        for (int b = 0; b < 2; b++)
            #pragma unroll
            for (int q = 0; q < 4; q++) oacc[a][b][q] = 0.f;

    for (int j = 0; j < 16; j++) {
        const int s = j & 1;
        __syncthreads();
        if (j < 15) { prep(s ^ 1, j + 1); CP_WAIT1(); }
        else        { CP_WAIT0(); }
        __syncthreads();

        float sacc[4][2][4];
        #pragma unroll
        for (int a = 0; a < 4; a++)
            #pragma unroll
            for (int b = 0; b < 2; b++)
                #pragma unroll
                for (int q = 0; q < 4; q++) sacc[a][b][q] = 0.f;

        const uint32_t ksb = ksu + (uint32_t)s * KVB;
        #pragma unroll
        for (int k16 = 0; k16 < 4; k16++) {
            uint32_t af[4];
            {
                int m = warp * 16 + (lane & 15);
                uint32_t addr = qsu + (uint32_t)m * 144 + k16 * 32 + ((lane >> 4) & 1) * 16;
                ldsm4(af[0], af[1], af[2], af[3], addr);
            }
            #pragma unroll
            for (int ig = 0; ig < 4; ig++) {
                uint32_t bf[4];
                int n = ig * 16 + (lane & 7) + ((lane >> 4) & 1) * 8;
                uint32_t addr = ksb + (uint32_t)n * 144 + k16 * 32 + ((lane >> 3) & 1) * 16;
                ldsm4(bf[0], bf[1], bf[2], bf[3], addr);
                mma_bf16(sacc[ig][0], af, bf + 0);
                mma_bf16(sacc[ig][1], af, bf + 2);
            }
        }

        #pragma unroll
        for (int ig = 0; ig < 4; ig++)
            #pragma unroll
            for (int hf = 0; hf < 2; hf++) {
                int cb = ig * 16 + hf * 8 + 2 * (lane & 3);
                float p0 = sm->psc[s][cb], p1 = sm->psc[s][cb + 1];
                sacc[ig][hf][0] = sacc[ig][hf][0] * 0.125f - p0;
                sacc[ig][hf][1] = sacc[ig][hf][1] * 0.125f - p1;
                sacc[ig][hf][2] = sacc[ig][hf][2] * 0.125f - p0;
                sacc[ig][hf][3] = sacc[ig][hf][3] * 0.125f - p1;
            }

        float mx0 = -1e30f, mx1 = -1e30f;
        #pragma unroll
        for (int ig = 0; ig < 4; ig++)
            #pragma unroll
            for (int hf = 0; hf < 2; hf++) {
                mx0 = fmaxf(mx0, fmaxf(sacc[ig][hf][0], sacc[ig][hf][1]));
                mx1 = fmaxf(mx1, fmaxf(sacc[ig][hf][2], sacc[ig][hf][3]));
            }
        #pragma unroll
        for (int off = 1; off <= 2; off <<= 1) {
            mx0 = fmaxf(mx0, __shfl_xor_sync(0xffffffffu, mx0, off));
            mx1 = fmaxf(mx1, __shfl_xor_sync(0xffffffffu, mx1, off));
        }
        float mn0 = fmaxf(m0, mx0), mn1 = fmaxf(m1, mx1);
        float f0 = __expf(m0 - mn0), f1 = __expf(m1 - mn1);
        float s0 = 0.f, s1 = 0.f;
        #pragma unroll
        for (int ig = 0; ig < 4; ig++)
            #pragma unroll
            for (int hf = 0; hf < 2; hf++) {
                sacc[ig][hf][0] = __expf(sacc[ig][hf][0] - mn0);
                sacc[ig][hf][1] = __expf(sacc[ig][hf][1] - mn0);
                sacc[ig][hf][2] = __expf(sacc[ig][hf][2] - mn1);
                sacc[ig][hf][3] = __expf(sacc[ig][hf][3] - mn1);
                s0 += sacc[ig][hf][0] + sacc[ig][hf][1];
                s1 += sacc[ig][hf][2] + sacc[ig][hf][3];
            }
        #pragma unroll
        for (int off = 1; off <= 2; off <<= 1) {
            s0 += __shfl_xor_sync(0xffffffffu, s0, off);
            s1 += __shfl_xor_sync(0xffffffffu, s1, off);
        }
        l0 = l0 * f0 + s0;  l1 = l1 * f1 + s1;
        m0 = mn0;           m1 = mn1;
        #pragma unroll
        for (int ig = 0; ig < 4; ig++)
            #pragma unroll
            for (int hf = 0; hf < 2; hf++) {
                oacc[ig][hf][0] *= f0; oacc[ig][hf][1] *= f0;
                oacc[ig][hf][2] *= f1; oacc[ig][hf][3] *= f1;
            }

        {
            __nv_bfloat16* psw = sm->Ps[warp];
            int r0 = lane >> 2;
            #pragma unroll
            for (int ig = 0; ig < 4; ig++)
                #pragma unroll
                for (int hf = 0; hf < 2; hf++) {
                    int cb = ig * 16 + hf * 8 + 2 * (lane & 3);
                    *reinterpret_cast<__nv_bfloat162*>(&psw[r0 * 72 + cb]) =
                        __floats2bfloat162_rn(sacc[ig][hf][0], sacc[ig][hf][1]);
                    *reinterpret_cast<__nv_bfloat162*>(&psw[(r0 + 8) * 72 + cb]) =
                        __floats2bfloat162_rn(sacc[ig][hf][2], sacc[ig][hf][3]);
                }
        }
        __syncwarp();

        const uint32_t vsb = vsu + (uint32_t)s * KVB;
        #pragma unroll
        for (int k16 = 0; k16 < 4; k16++) {
            uint32_t af[4];
            {
                int m = lane & 15;
                uint32_t addr = psu + (uint32_t)m * 144 + k16 * 32 + ((lane >> 4) & 1) * 16;
                ldsm4(af[0], af[1], af[2], af[3], addr);
            }
            #pragma unroll
            for (int ig = 0; ig < 4; ig++) {
                uint32_t bf[4];
                int key = k16 * 16 + ((lane >> 3) & 1) * 8 + (lane & 7);
                uint32_t addr = vsb + (uint32_t)key * 144 + ig * 32 + ((lane >> 4) & 1) * 16;
                ldsm4t(bf[0], bf[1], bf[2], bf[3], addr);
                mma_bf16(oacc[ig][0], af, bf + 0);
                mma_bf16(oacc[ig][1], af, bf + 2);
            }
        }
    }

    float inv0 = 1.f / l0, inv1 = 1.f / l1;
    long gi = (long)zb * NN_ + mt * 128 + warp * 16 + (lane >> 2);
    #pragma unroll
    for (int ig = 0; ig < 4; ig++)
        #pragma unroll
        for (int hf = 0; hf < 2; hf++) {
            int c = zh * 64 + ig * 16 + hf * 8 + 2 * (lane & 3);
            float2 a; a.x = oacc[ig][hf][0] * inv0; a.y = oacc[ig][hf][1] * inv0;
            float2 b; b.x = oacc[ig][hf][2] * inv1; b.y = oacc[ig][hf][3] * inv1;
            *reinterpret_cast<float2*>(&o[gi * DD + c]) = a;
            *reinterpret_cast<float2*>(&o[(gi + 8) * DD + c]) = b;
        }
}

// ---------------- launch ----------------
extern "C" void kernel_launch(void* const* d_in, const int* in_sizes, int n_in,
                              void* d_out, int out_size)
{
    const float* x      = (const float*)d_in[0];
    const float* coords = (const float*)d_in[1];
    const float* ln1_g  = (const float*)d_in[2];
    const float* ln1_b  = (const float*)d_in[3];
    const float* qkv_w  = (const float*)d_in[4];
    const float* qkv_b  = (const float*)d_in[5];
    const float* rel_w  = (const float*)d_in[6];
    const float* ln2_g  = (const float*)d_in[7];
    const float* ln2_b  = (const float*)d_in[8];
    const float* win_w  = (const float*)d_in[9];
    const float* win_b  = (const float*)d_in[10];
    const float* wout_w = (const float*)d_in[11];
    const float* wout_b = (const float*)d_in[12];
    float* out = (float*)d_out;

    float* S = nullptr;
    cudaGetSymbolAddress((void**)&S, g_scratch);
    float* p   = S + OFF_P;
    float* xm  = S + OFF_XM;
    float* o   = S + OFF_O;
    __nv_bfloat16* qkvbf = (__nv_bfloat16*)(S + OFF_QKVBF);
    __nv_bfloat16* hbf   = (__nv_bfloat16*)(S + OFF_HBF);
    __nv_bfloat16* wqbf  = (__nv_bfloat16*)(S + OFF_WQ);
    __nv_bfloat16* wibf  = (__nv_bfloat16*)(S + OFF_WI);
    __nv_bfloat16* wobf  = (__nv_bfloat16*)(S + OFF_WO);
    __nv_bfloat16* actbf = (__nv_bfloat16*)(S + OFF_ACTBF);

    cudaFuncSetAttribute(fa_kernel, cudaFuncAttributeMaxDynamicSharedMemorySize,
                         (int)FA_SMEM_BYTES);
    cudaFuncSetAttribute((tgemm<true, 128>),  cudaFuncAttributeMaxDynamicSharedMemorySize, TG_SMEM_BYTES(128));
    cudaFuncSetAttribute((tgemm<false, 64>),  cudaFuncAttributeMaxDynamicSharedMemorySize, TG_SMEM_BYTES(64));
    cudaFuncSetAttribute(ffn_in_kernel, cudaFuncAttributeMaxDynamicSharedMemorySize, FI_SMEM_BYTES);

    // 0) weight converts + p bias, one launch
    cvt3p_kernel<<<(CVT_THREADS + ZHN*NN_ + 255)/256, 256>>>(
        qkv_w, win_w, wout_w, wqbf, coords, rel_w, p);

    // 1) h = LN1(x) -> bf16
    ln_kernel<<<ROWS, 256>>>(x, nullptr, ln1_g, ln1_b, hbf, nullptr);

    // 2) qkv = h @ qkv_w^T + qkv_b -> bf16
    tgemm<true, 128><<<dim3(D3/128, ROWS/128), 256, TG_SMEM_BYTES(128)>>>(
        hbf, wqbf, qkvbf, DD, DD, D3, DD, qkv_b, nullptr);

    // 3-5) fused attention -> o (fp32)
    fa_kernel<<<dim3(8, ZHN), 256, FA_SMEM_BYTES>>>(qkvbf, p, o);

    // 6) xm = x + o ; h2 = LN2(xm) -> bf16
    ln_kernel<<<ROWS, 256>>>(x, o, ln2_g, ln2_b, hbf, xm);

    // 7+8) act = silu(h2 Wu^T + bu) * (h2 Wg^T + bg) -> bf16 (fused)
    ffn_in_kernel<<<dim3(HID/64, ROWS/128), 256, FI_SMEM_BYTES>>>(hbf, wibf, actbf, win_b);

    // 9) out = act @ wout_w^T + wout_b + xm -> fp32  (BM=64: 384 CTAs, better wave shape)
    tgemm<false, 64><<<dim3(DD/128, ROWS/64), 256, TG_SMEM_BYTES(64)>>>(
        actbf, wobf, out, HID, HID, DD, HID, wout_b, xm);
}

// round 14
// speedup vs baseline: 1.5850x; 1.0060x over previous
#include <cuda_runtime.h>
#include <cuda_bf16.h>
#include <math.h>
#include <stdint.h>

// ---------------- problem constants ----------------
#define BB   4
#define NN_  1024
#define DD   768
#define HH   12
#define DH   64
#define HID  2048
#define D3   2304          // 3*D
#define ROWS (BB*NN_)      // 4096
#define ZHN  (BB*HH)       // 48

// ---------------- scratch ----------------
#define OFF_P      0L
#define OFF_XM     49152L
#define OFF_O      3194880L
#define OFF_QKVBF  6340608L
#define OFF_HBF    11059200L
#define OFF_WQ     12632064L
#define OFF_WI     13516800L
#define OFF_WO     15089664L
#define OFF_ACTBF  15876096L
#define SCRATCH_TOTAL 20070400L   // ~80 MB

__device__ float g_scratch[SCRATCH_TOTAL];

// ---------------- PTX helpers ----------------
#define CP_ASYNC16(dst, src) asm volatile("cp.async.cg.shared.global [%0], [%1], 16;\n" :: "r"(dst), "l"(src))
#define CP_COMMIT()  asm volatile("cp.async.commit_group;\n")
#define CP_WAIT1()   asm volatile("cp.async.wait_group 1;\n" ::: "memory")
#define CP_WAIT0()   asm volatile("cp.async.wait_group 0;\n" ::: "memory")

__device__ __forceinline__ void ldsm4(uint32_t& r0, uint32_t& r1, uint32_t& r2, uint32_t& r3, uint32_t addr) {
    asm volatile("ldmatrix.sync.aligned.m8n8.x4.shared.b16 {%0,%1,%2,%3}, [%4];\n"
                 : "=r"(r0), "=r"(r1), "=r"(r2), "=r"(r3) : "r"(addr));
}
__device__ __forceinline__ void ldsm4t(uint32_t& r0, uint32_t& r1, uint32_t& r2, uint32_t& r3, uint32_t addr) {
    asm volatile("ldmatrix.sync.aligned.m8n8.x4.trans.shared.b16 {%0,%1,%2,%3}, [%4];\n"
                 : "=r"(r0), "=r"(r1), "=r"(r2), "=r"(r3) : "r"(addr));
}
__device__ __forceinline__ void mma_bf16(float* c, const uint32_t* a, const uint32_t* b) {
    asm volatile(
        "mma.sync.aligned.m16n8k16.row.col.f32.bf16.bf16.f32 "
        "{%0,%1,%2,%3},{%4,%5,%6,%7},{%8,%9},{%0,%1,%2,%3};\n"
        : "+f"(c[0]), "+f"(c[1]), "+f"(c[2]), "+f"(c[3])
        : "r"(a[0]), "r"(a[1]), "r"(a[2]), "r"(a[3]), "r"(b[0]), "r"(b[1]));
}

// ---------------- block reduce (256 threads) ----------------
__device__ __forceinline__ float blk_reduce(float v, float* sm, int op) {
    __syncthreads();
    #pragma unroll
    for (int o = 16; o > 0; o >>= 1) {
        float t = __shfl_xor_sync(0xffffffffu, v, o);
        v = op ? fmaxf(v, t) : (v + t);
    }
    int lane = threadIdx.x & 31, w = threadIdx.x >> 5;
    if (lane == 0) sm[w] = v;
    __syncthreads();
    float r = sm[0];
    #pragma unroll
    for (int i = 1; i < 8; i++) r = op ? fmaxf(r, sm[i]) : (r + sm[i]);
    return r;
}

// ---------------- LN body (res optional), used by ln_kernel and pre_kernel ----------------
__device__ __forceinline__ void ln_body(
    const float* __restrict__ x, const float* __restrict__ res,
    const float* __restrict__ g, const float* __restrict__ b,
    __nv_bfloat16* __restrict__ out, float* __restrict__ sum_out,
    long row, float* sm)
{
    int t = threadIdx.x;
    const float* xr = x + row * DD;
    float v[3];
    float s = 0.f;
    #pragma unroll
    for (int i = 0; i < 3; i++) {
        int idx = t + i * 256;
        float val = xr[idx];
        if (res) val += res[row * DD + idx];
        v[i] = val; s += val;
    }
    float mean = blk_reduce(s, sm, 0) * (1.f / 768.f);
    float vs = 0.f;
    #pragma unroll
    for (int i = 0; i < 3; i++) { float d = v[i] - mean; vs += d * d; }
    float var = blk_reduce(vs, sm, 0) * (1.f / 768.f);
    float rstd = rsqrtf(var + 1e-5f);
    #pragma unroll
    for (int i = 0; i < 3; i++) {
        int idx = t + i * 256;
        if (sum_out) sum_out[row * DD + idx] = v[i];
        out[row * DD + idx] = __float2bfloat16_rn((v[i] - mean) * rstd * g[idx] + b[idx]);
    }
}

__global__ __launch_bounds__(256) void ln_kernel(
    const float* __restrict__ x, const float* __restrict__ res,
    const float* __restrict__ g, const float* __restrict__ b,
    __nv_bfloat16* __restrict__ out, float* __restrict__ sum_out)
{
    __shared__ float sm[32];
    ln_body(x, res, g, b, out, sum_out, blockIdx.x, sm);
}

// ---------------- pre_kernel: LN1 + weight converts + p, one launch ----------------
// Blocks [0, ROWS): LN1 rows. Blocks >= ROWS: cvt range then p range.
#define N_WQ (D3*DD)
#define N_WI (2*HID*DD)
#define N_WO (DD*HID)
#define N_CVT (N_WQ + N_WI + N_WO)   // 6488064
#define CVT_THREADS (N_CVT/4)        // 1622016 (multiple of 256)
#define PRE_BLOCKS (ROWS + (CVT_THREADS + ZHN*NN_)/256)   // 4096 + 6528

__global__ __launch_bounds__(256) void pre_kernel(
    const float* __restrict__ x, const float* __restrict__ ln1_g,
    const float* __restrict__ ln1_b, __nv_bfloat16* __restrict__ hbf,
    const float* __restrict__ wq, const float* __restrict__ wi,
    const float* __restrict__ wo, __nv_bfloat16* __restrict__ wout_bf,
    const float* __restrict__ coords, const float* __restrict__ rel_w,
    float* __restrict__ p)
{
    __shared__ float sm[32];
    int bid = blockIdx.x;
    if (bid < ROWS) {
        ln_body(x, nullptr, ln1_g, ln1_b, hbf, nullptr, bid, sm);
        return;
    }
    long gt = (long)(bid - ROWS) * 256 + threadIdx.x;
    if (gt < CVT_THREADS) {
        long i = gt * 4;
        const float* src;
        long j = i;
        if (j < N_WQ)             { src = wq; }
        else if (j < N_WQ + N_WI) { src = wi; j -= N_WQ; }
        else                      { src = wo; j -= (long)N_WQ + N_WI; }
        float4 v = *reinterpret_cast<const float4*>(src + j);
        *reinterpret_cast<__nv_bfloat162*>(wout_bf + i)     = __floats2bfloat162_rn(v.x, v.y);
        *reinterpret_cast<__nv_bfloat162*>(wout_bf + i + 2) = __floats2bfloat162_rn(v.z, v.w);
    } else {
        int idx = (int)(gt - CVT_THREADS);
        if (idx >= ZHN * NN_) return;
        int n = idx & (NN_ - 1);
        int h = (idx >> 10) % HH;
        int b = idx / (HH * NN_);
        const float* c = coords + ((long)b * NN_ + n) * 3;
        const float* w = rel_w + h * 3;
        p[idx] = c[0] * w[0] + c[1] * w[1] + c[2] * w[2];
    }
}

// =====================================================================
// bf16 tensor-core GEMM: C = A(MxK) * B^T + bias [+ res].
// BMt x 128 tile, BK=64, 8 warps of (BMt/2)x32, 2 CTAs/SM, dynamic smem.
// =====================================================================
template<bool OBF, int BMt>
__global__ __launch_bounds__(256, 2) void tgemm(
    const __nv_bfloat16* __restrict__ A, const __nv_bfloat16* __restrict__ B,
    void* __restrict__ Cv,
    int lda, int ldb, int ldc, int K,
    const float* __restrict__ bias, const float* __restrict__ residual)
{
    constexpr int LDSB = 72;
    constexpr int WMR  = BMt / 2;
    constexpr int MF   = WMR / 16;
    constexpr int AITER = BMt / 32;
    constexpr uint32_t ASTG = BMt * LDSB * 2;
    constexpr uint32_t BSTG = 128 * LDSB * 2;
    extern __shared__ __nv_bfloat16 dsm[];

    const int tid  = threadIdx.x;
    const int lane = tid & 31;
    const int warp = tid >> 5;
    const int wm = warp >> 2;
    const int wn = warp & 3;

    const int row0 = blockIdx.y * BMt;
    const int col0 = blockIdx.x * 128;

    const uint32_t asu = (uint32_t)__cvta_generic_to_shared(dsm);
    const uint32_t bsu = asu + 2 * ASTG;

    float acc[MF][4][4];
    #pragma unroll
    for (int i = 0; i < MF; i++)
        #pragma unroll
        for (int j = 0; j < 4; j++)
            #pragma unroll
            for (int q = 0; q < 4; q++) acc[i][j][q] = 0.f;

    const int KT = K >> 6;

    auto prefetch = [&](int s, int kt) {
        const __nv_bfloat16* Ag = A + (long)row0 * lda + kt * 64;
        const __nv_bfloat16* Bg = B + (long)col0 * ldb + kt * 64;
        #pragma unroll
        for (int i = 0; i < AITER; i++) {
            int l = tid + 256 * i;
            int r = l >> 3, c = (l & 7) << 3;
            CP_ASYNC16(asu + s * ASTG + (uint32_t)(r * LDSB + c) * 2, Ag + (long)r * lda + c);
        }
        #pragma unroll
        for (int i = 0; i < 4; i++) {
            int l = tid + 256 * i;
            int r = l >> 3, c = (l & 7) << 3;
            CP_ASYNC16(bsu + s * BSTG + (uint32_t)(r * LDSB + c) * 2, Bg + (long)r * ldb + c);
        }
        CP_COMMIT();
    };

    prefetch(0, 0);

    for (int kt = 0; kt < KT; kt++) {
        if (kt + 1 < KT) { prefetch((kt + 1) & 1, kt + 1); CP_WAIT1(); }
        else             { CP_WAIT0(); }
        __syncthreads();

        const uint32_t ab = asu + (uint32_t)(kt & 1) * ASTG;
        const uint32_t bb = bsu + (uint32_t)(kt & 1) * BSTG;

        #pragma unroll
        for (int k16 = 0; k16 < 4; k16++) {
            uint32_t af[MF][4];
            #pragma unroll
            for (int im = 0; im < MF; im++) {
                int m = wm * WMR + im * 16 + (lane & 15);
                uint32_t addr = ab + (uint32_t)m * (LDSB * 2) + k16 * 32 + ((lane >> 4) & 1) * 16;
                ldsm4(af[im][0], af[im][1], af[im][2], af[im][3], addr);
            }
            #pragma unroll
            for (int ig = 0; ig < 2; ig++) {
                uint32_t bf[4];
                int n = wn * 32 + ig * 16 + (lane & 7) + ((lane >> 4) & 1) * 8;
                uint32_t addr = bb + (uint32_t)n * (LDSB * 2) + k16 * 32 + ((lane >> 3) & 1) * 16;
                ldsm4(bf[0], bf[1], bf[2], bf[3], addr);
                #pragma unroll
                for (int im = 0; im < MF; im++) {
                    mma_bf16(acc[im][ig * 2 + 0], af[im], bf + 0);
                    mma_bf16(acc[im][ig * 2 + 1], af[im], bf + 2);
                }
            }
        }
        __syncthreads();
    }

    #pragma unroll
    for (int im = 0; im < MF; im++) {
        int mrow = row0 + wm * WMR + im * 16 + (lane >> 2);
        #pragma unroll
        for (int jg = 0; jg < 4; jg++) {
            int ncol = col0 + wn * 32 + (jg >> 1) * 16 + (jg & 1) * 8 + 2 * (lane & 3);
            float b0 = 0.f, b1 = 0.f;
            if (bias) { b0 = bias[ncol]; b1 = bias[ncol + 1]; }
            #pragma unroll
            for (int half = 0; half < 2; half++) {
                long r = mrow + half * 8;
                float v0 = acc[im][jg][half * 2 + 0] + b0;
                float v1 = acc[im][jg][half * 2 + 1] + b1;
                if (residual) {
                    v0 += residual[r * ldc + ncol];
                    v1 += residual[r * ldc + ncol + 1];
                }
                if (OBF) {
                    __nv_bfloat16* C = (__nv_bfloat16*)Cv;
                    *reinterpret_cast<__nv_bfloat162*>(&C[r * ldc + ncol]) =
                        __floats2bfloat162_rn(v0, v1);
                } else {
                    float* C = (float*)Cv;
                    float2 vv; vv.x = v0; vv.y = v1;
                    *reinterpret_cast<float2*>(&C[r * ldc + ncol]) = vv;
                }
            }
        }
    }
}
#define TG_SMEM_BYTES(BM_)  ((2 * (BM_) + 2 * 128) * 72 * 2)

// =====================================================================
// Fused FFN-in + SwiGLU (BK=64, stride 72, 2 CTAs/SM, dynamic smem).
// =====================================================================
__global__ __launch_bounds__(256, 2) void ffn_in_kernel(
    const __nv_bfloat16* __restrict__ A, const __nv_bfloat16* __restrict__ B,
    __nv_bfloat16* __restrict__ act, const float* __restrict__ bias)
{
    constexpr int LDSB = 72;
    constexpr uint32_t ASTG = 128 * LDSB * 2;
    constexpr uint32_t BSTG = 64 * LDSB * 2;
    extern __shared__ __nv_bfloat16 dsm[];

    const int tid  = threadIdx.x;
    const int lane = tid & 31;
    const int warp = tid >> 5;
    const int wm = warp >> 2;
    const int wn = warp & 3;

    const int row0 = blockIdx.y * 128;
    const int col0 = blockIdx.x * 64;

    const uint32_t asu = (uint32_t)__cvta_generic_to_shared(dsm);
    const uint32_t buu = asu + 2 * ASTG;
    const uint32_t bgu = buu + 2 * BSTG;

    float accu[4][2][4], accg[4][2][4];
    #pragma unroll
    for (int i = 0; i < 4; i++)
        #pragma unroll
        for (int j = 0; j < 2; j++)
            #pragma unroll
            for (int q = 0; q < 4; q++) { accu[i][j][q] = 0.f; accg[i][j][q] = 0.f; }

    const int KT = DD >> 6;   // 12

    auto prefetch = [&](int s, int kt) {
        const __nv_bfloat16* Ag = A + (long)row0 * DD + kt * 64;
        #pragma unroll
        for (int i = 0; i < 4; i++) {
            int l = tid + 256 * i;
            int r = l >> 3, c = (l & 7) << 3;
            CP_ASYNC16(asu + s * ASTG + (uint32_t)(r * LDSB + c) * 2, Ag + (long)r * DD + c);
        }
        #pragma unroll
        for (int i = 0; i < 2; i++) {
            int l = tid + 256 * i;
            int r = l >> 3, c = (l & 7) << 3;
            uint32_t off = (uint32_t)(r * LDSB + c) * 2;
            CP_ASYNC16(buu + s * BSTG + off, B + (long)(col0 + r) * DD + kt * 64 + c);
            CP_ASYNC16(bgu + s * BSTG + off, B + (long)(HID + col0 + r) * DD + kt * 64 + c);
        }
        CP_COMMIT();
    };

    prefetch(0, 0);

    for (int kt = 0; kt < KT; kt++) {
        if (kt + 1 < KT) { prefetch((kt + 1) & 1, kt + 1); CP_WAIT1(); }
        else             { CP_WAIT0(); }
        __syncthreads();

        const uint32_t ab  = asu + (uint32_t)(kt & 1) * ASTG;
        const uint32_t bub = buu + (uint32_t)(kt & 1) * BSTG;
        const uint32_t bgb = bgu + (uint32_t)(kt & 1) * BSTG;

        #pragma unroll
        for (int k16 = 0; k16 < 4; k16++) {
            uint32_t af[4][4];
            #pragma unroll
            for (int im = 0; im < 4; im++) {
                int m = wm * 64 + im * 16 + (lane & 15);
                uint32_t addr = ab + (uint32_t)m * (LDSB * 2) + k16 * 32 + ((lane >> 4) & 1) * 16;
                ldsm4(af[im][0], af[im][1], af[im][2], af[im][3], addr);
            }
            int n = wn * 16 + (lane & 7) + ((lane >> 4) & 1) * 8;
            uint32_t off = (uint32_t)n * (LDSB * 2) + k16 * 32 + ((lane >> 3) & 1) * 16;
            uint32_t bfu[4], bfg[4];
            ldsm4(bfu[0], bfu[1], bfu[2], bfu[3], bub + off);
            ldsm4(bfg[0], bfg[1], bfg[2], bfg[3], bgb + off);
            #pragma unroll
            for (int im = 0; im < 4; im++) {
                mma_bf16(accu[im][0], af[im], bfu + 0);
                mma_bf16(accu[im][1], af[im], bfu + 2);
                mma_bf16(accg[im][0], af[im], bfg + 0);
                mma_bf16(accg[im][1], af[im], bfg + 2);
            }
        }
        __syncthreads();
    }

    #pragma unroll
    for (int im = 0; im < 4; im++) {
        int mrow = row0 + wm * 64 + im * 16 + (lane >> 2);
        #pragma unroll
        for (int jg = 0; jg < 2; jg++) {
            int col = col0 + wn * 16 + jg * 8 + 2 * (lane & 3);
            float bu0 = bias[col],       bu1 = bias[col + 1];
            float bg0 = bias[HID + col], bg1 = bias[HID + col + 1];
            #pragma unroll
            for (int half = 0; half < 2; half++) {
                long r = mrow + half * 8;
                float u0 = accu[im][jg][half * 2 + 0] + bu0;
                float u1 = accu[im][jg][half * 2 + 1] + bu1;
                float g0 = accg[im][jg][half * 2 + 0] + bg0;
                float g1 = accg[im][jg][half * 2 + 1] + bg1;
                float a0 = u0 / (1.f + __expf(-u0)) * g0;
                float a1 = u1 / (1.f + __expf(-u1)) * g1;
                *reinterpret_cast<__nv_bfloat162*>(&act[r * HID + col]) =
                    __floats2bfloat162_rn(a0, a1);
            }
        }
    }
}
#define FI_SMEM_BYTES ((2 * 128 + 2 * 64 + 2 * 64) * 72 * 2)   // 73728

// =====================================================================
// Fused flash attention, bf16 MMA. 64 q-rows/CTA, 128 threads (4 warps),
// 4 CTAs/SM. Per-warp code identical to the validated 128-row version.
// =====================================================================
struct FaSmem {
    __nv_bfloat16 Qs[64 * 72];
    __nv_bfloat16 Ks[2][64 * 72];
    __nv_bfloat16 Vs[2][64 * 72];
    __nv_bfloat16 Ps[4][16 * 72];
    float psc[2][64];
};
#define FA_SMEM_BYTES (sizeof(FaSmem))

__global__ __launch_bounds__(128, 4) void fa_kernel(
    const __nv_bfloat16* __restrict__ qkv, const float* __restrict__ p,
    float* __restrict__ o)
{
    extern __shared__ float smf[];
    FaSmem* sm = reinterpret_cast<FaSmem*>(smf);
    const int tid = threadIdx.x, lane = tid & 31, warp = tid >> 5;   // warp 0..3
    const int mt = blockIdx.x;       // 0..15
    const int z  = blockIdx.y;       // 0..47
    const int zb = z / HH, zh = z % HH;

    const __nv_bfloat16* Qg = qkv + ((long)zb * NN_ + mt * 64) * D3 + zh * 64;
    const __nv_bfloat16* Kg = qkv + (long)zb * NN_ * D3 + DD + zh * 64;
    const __nv_bfloat16* Vg = qkv + (long)zb * NN_ * D3 + 2 * DD + zh * 64;
    const float* pg = p + (long)z * NN_;

    const uint32_t qsu  = (uint32_t)__cvta_generic_to_shared(sm->Qs);
    const uint32_t ksu  = (uint32_t)__cvta_generic_to_shared(sm->Ks[0]);
    const uint32_t vsu  = (uint32_t)__cvta_generic_to_shared(sm->Vs[0]);
    const uint32_t psu  = (uint32_t)__cvta_generic_to_shared(sm->Ps[warp]);
    const uint32_t pscu = (uint32_t)__cvta_generic_to_shared(sm->psc[0]);
    constexpr uint32_t KVB = 64 * 72 * 2;

    auto prep = [&](int s, int j) {
        #pragma unroll
        for (int i = 0; i < 4; i++) {
            int l = tid + 128 * i;
            int r = l >> 3, c = (l & 7) << 3;
            CP_ASYNC16(ksu + (uint32_t)s * KVB + (uint32_t)(r * 72 + c) * 2,
                       Kg + (long)(j * 64 + r) * D3 + c);
            CP_ASYNC16(vsu + (uint32_t)s * KVB + (uint32_t)(r * 72 + c) * 2,
                       Vg + (long)(j * 64 + r) * D3 + c);
        }
        if (tid < 16)
            CP_ASYNC16(pscu + (uint32_t)s * 256 + tid * 16, pg + j * 64 + tid * 4);
        CP_COMMIT();
    };

    // Q load: 64 rows x 64 cols bf16 = 512 x 16B
    #pragma unroll
    for (int i = 0; i < 4; i++) {
        int l = tid + 128 * i;
        int r = l >> 3, c = (l & 7) << 3;
        CP_ASYNC16(qsu + (uint32_t)(r * 72 + c) * 2, Qg + (long)r * D3 + c);
    }
    prep(0, 0);

    float m0 = -1e30f, m1 = -1e30f, l0 = 0.f, l1 = 0.f;
    float oacc[4][2][4];
    #pragma unroll
    for (int a = 0; a < 4; a++)
        #pragma unroll
        for (int b = 0; b < 2; b++)
            #pragma unroll
            for (int q = 0; q < 4; q++) oacc[a][b][q] = 0.f;

    for (int j = 0; j < 16; j++) {
        const int s = j & 1;
        __syncthreads();
        if (j < 15) { prep(s ^ 1, j + 1); CP_WAIT1(); }
        else        { CP_WAIT0(); }
        __syncthreads();

        float sacc[4][2][4];
        #pragma unroll
        for (int a = 0; a < 4; a++)
            #pragma unroll
            for (int b = 0; b < 2; b++)
                #pragma unroll
                for (int q = 0; q < 4; q++) sacc[a][b][q] = 0.f;

        const uint32_t ksb = ksu + (uint32_t)s * KVB;
        #pragma unroll
        for (int k16 = 0; k16 < 4; k16++) {
            uint32_t af[4];
            {
                int m = warp * 16 + (lane & 15);
                uint32_t addr = qsu + (uint32_t)m * 144 + k16 * 32 + ((lane >> 4) & 1) * 16;
                ldsm4(af[0], af[1], af[2], af[3], addr);
            }
            #pragma unroll
            for (int ig = 0; ig < 4; ig++) {
                uint32_t bf[4];
                int n = ig * 16 + (lane & 7) + ((lane >> 4) & 1) * 8;
                uint32_t addr = ksb + (uint32_t)n * 144 + k16 * 32 + ((lane >> 3) & 1) * 16;
                ldsm4(bf[0], bf[1], bf[2], bf[3], addr);
                mma_bf16(sacc[ig][0], af, bf + 0);
                mma_bf16(sacc[ig][1], af, bf + 2);
            }
        }

        #pragma unroll
        for (int ig = 0; ig < 4; ig++)
            #pragma unroll
            for (int hf = 0; hf < 2; hf++) {
                int cb = ig * 16 + hf * 8 + 2 * (lane & 3);
                float p0 = sm->psc[s][cb], p1 = sm->psc[s][cb + 1];
                sacc[ig][hf][0] = sacc[ig][hf][0] * 0.125f - p0;
                sacc[ig][hf][1] = sacc[ig][hf][1] * 0.125f - p1;
                sacc[ig][hf][2] = sacc[ig][hf][2] * 0.125f - p0;
                sacc[ig][hf][3] = sacc[ig][hf][3] * 0.125f - p1;
            }

        float mx0 = -1e30f, mx1 = -1e30f;
        #pragma unroll
        for (int ig = 0; ig < 4; ig++)
            #pragma unroll
            for (int hf = 0; hf < 2; hf++) {
                mx0 = fmaxf(mx0, fmaxf(sacc[ig][hf][0], sacc[ig][hf][1]));
                mx1 = fmaxf(mx1, fmaxf(sacc[ig][hf][2], sacc[ig][hf][3]));
            }
        #pragma unroll
        for (int off = 1; off <= 2; off <<= 1) {
            mx0 = fmaxf(mx0, __shfl_xor_sync(0xffffffffu, mx0, off));
            mx1 = fmaxf(mx1, __shfl_xor_sync(0xffffffffu, mx1, off));
        }
        float mn0 = fmaxf(m0, mx0), mn1 = fmaxf(m1, mx1);
        float f0 = __expf(m0 - mn0), f1 = __expf(m1 - mn1);
        float s0 = 0.f, s1 = 0.f;
        #pragma unroll
        for (int ig = 0; ig < 4; ig++)
            #pragma unroll
            for (int hf = 0; hf < 2; hf++) {
                sacc[ig][hf][0] = __expf(sacc[ig][hf][0] - mn0);
                sacc[ig][hf][1] = __expf(sacc[ig][hf][1] - mn0);
                sacc[ig][hf][2] = __expf(sacc[ig][hf][2] - mn1);
                sacc[ig][hf][3] = __expf(sacc[ig][hf][3] - mn1);
                s0 += sacc[ig][hf][0] + sacc[ig][hf][1];
                s1 += sacc[ig][hf][2] + sacc[ig][hf][3];
            }
        #pragma unroll
        for (int off = 1; off <= 2; off <<= 1) {
            s0 += __shfl_xor_sync(0xffffffffu, s0, off);
            s1 += __shfl_xor_sync(0xffffffffu, s1, off);
        }
        l0 = l0 * f0 + s0;  l1 = l1 * f1 + s1;
        m0 = mn0;           m1 = mn1;
        #pragma unroll
        for (int ig = 0; ig < 4; ig++)
            #pragma unroll
            for (int hf = 0; hf < 2; hf++) {
                oacc[ig][hf][0] *= f0; oacc[ig][hf][1] *= f0;
                oacc[ig][hf][2] *= f1; oacc[ig][hf][3] *= f1;
            }

        {
            __nv_bfloat16* psw = sm->Ps[warp];
            int r0 = lane >> 2;
            #pragma unroll
            for (int ig = 0; ig < 4; ig++)
                #pragma unroll
                for (int hf = 0; hf < 2; hf++) {
                    int cb = ig * 16 + hf * 8 + 2 * (lane & 3);
                    *reinterpret_cast<__nv_bfloat162*>(&psw[r0 * 72 + cb]) =
                        __floats2bfloat162_rn(sacc[ig][hf][0], sacc[ig][hf][1]);
                    *reinterpret_cast<__nv_bfloat162*>(&psw[(r0 + 8) * 72 + cb]) =
                        __floats2bfloat162_rn(sacc[ig][hf][2], sacc[ig][hf][3]);
                }
        }
        __syncwarp();

        const uint32_t vsb = vsu + (uint32_t)s * KVB;
        #pragma unroll
        for (int k16 = 0; k16 < 4; k16++) {
            uint32_t af[4];
            {
                int m = lane & 15;
                uint32_t addr = psu + (uint32_t)m * 144 + k16 * 32 + ((lane >> 4) & 1) * 16;
                ldsm4(af[0], af[1], af[2], af[3], addr);
            }
            #pragma unroll
            for (int ig = 0; ig < 4; ig++) {
                uint32_t bf[4];
                int key = k16 * 16 + ((lane >> 3) & 1) * 8 + (lane & 7);
                uint32_t addr = vsb + (uint32_t)key * 144 + ig * 32 + ((lane >> 4) & 1) * 16;
                ldsm4t(bf[0], bf[1], bf[2], bf[3], addr);
                mma_bf16(oacc[ig][0], af, bf + 0);
                mma_bf16(oacc[ig][1], af, bf + 2);
            }
        }
    }

    float inv0 = 1.f / l0, inv1 = 1.f / l1;
    long gi = (long)zb * NN_ + mt * 64 + warp * 16 + (lane >> 2);
    #pragma unroll
    for (int ig = 0; ig < 4; ig++)
        #pragma unroll
        for (int hf = 0; hf < 2; hf++) {
            int c = zh * 64 + ig * 16 + hf * 8 + 2 * (lane & 3);
            float2 a; a.x = oacc[ig][hf][0] * inv0; a.y = oacc[ig][hf][1] * inv0;
            float2 b; b.x = oacc[ig][hf][2] * inv1; b.y = oacc[ig][hf][3] * inv1;
            *reinterpret_cast<float2*>(&o[gi * DD + c]) = a;
            *reinterpret_cast<float2*>(&o[(gi + 8) * DD + c]) = b;
        }
}

// ---------------- launch ----------------
extern "C" void kernel_launch(void* const* d_in, const int* in_sizes, int n_in,
                              void* d_out, int out_size)
{
    const float* x      = (const float*)d_in[0];
    const float* coords = (const float*)d_in[1];
    const float* ln1_g  = (const float*)d_in[2];
    const float* ln1_b  = (const float*)d_in[3];
    const float* qkv_w  = (const float*)d_in[4];
    const float* qkv_b  = (const float*)d_in[5];
    const float* rel_w  = (const float*)d_in[6];
    const float* ln2_g  = (const float*)d_in[7];
    const float* ln2_b  = (const float*)d_in[8];
    const float* win_w  = (const float*)d_in[9];
    const float* win_b  = (const float*)d_in[10];
    const float* wout_w = (const float*)d_in[11];
    const float* wout_b = (const float*)d_in[12];
    float* out = (float*)d_out;

    float* S = nullptr;
    cudaGetSymbolAddress((void**)&S, g_scratch);
    float* p   = S + OFF_P;
    float* xm  = S + OFF_XM;
    float* o   = S + OFF_O;
    __nv_bfloat16* qkvbf = (__nv_bfloat16*)(S + OFF_QKVBF);
    __nv_bfloat16* hbf   = (__nv_bfloat16*)(S + OFF_HBF);
    __nv_bfloat16* wqbf  = (__nv_bfloat16*)(S + OFF_WQ);
    __nv_bfloat16* wibf  = (__nv_bfloat16*)(S + OFF_WI);
    __nv_bfloat16* wobf  = (__nv_bfloat16*)(S + OFF_WO);
    __nv_bfloat16* actbf = (__nv_bfloat16*)(S + OFF_ACTBF);

    cudaFuncSetAttribute(fa_kernel, cudaFuncAttributeMaxDynamicSharedMemorySize,
                         (int)FA_SMEM_BYTES);
    cudaFuncSetAttribute((tgemm<true, 128>),  cudaFuncAttributeMaxDynamicSharedMemorySize, TG_SMEM_BYTES(128));
    cudaFuncSetAttribute((tgemm<false, 64>),  cudaFuncAttributeMaxDynamicSharedMemorySize, TG_SMEM_BYTES(64));
    cudaFuncSetAttribute(ffn_in_kernel, cudaFuncAttributeMaxDynamicSharedMemorySize, FI_SMEM_BYTES);

    // 0) LN1 + weight converts + p bias, one launch
    pre_kernel<<<PRE_BLOCKS, 256>>>(x, ln1_g, ln1_b, hbf,
                                    qkv_w, win_w, wout_w, wqbf,
                                    coords, rel_w, p);

    // 1) qkv = h @ qkv_w^T + qkv_b -> bf16
    tgemm<true, 128><<<dim3(D3/128, ROWS/128), 256, TG_SMEM_BYTES(128)>>>(
        hbf, wqbf, qkvbf, DD, DD, D3, DD, qkv_b, nullptr);

    // 2-4) fused attention -> o (fp32); 64-row q tiles, 768 CTAs
    fa_kernel<<<dim3(16, ZHN), 128, FA_SMEM_BYTES>>>(qkvbf, p, o);

    // 5) xm = x + o ; h2 = LN2(xm) -> bf16
    ln_kernel<<<ROWS, 256>>>(x, o, ln2_g, ln2_b, hbf, xm);

    // 6+7) act = silu(h2 Wu^T + bu) * (h2 Wg^T + bg) -> bf16 (fused)
    ffn_in_kernel<<<dim3(HID/64, ROWS/128), 256, FI_SMEM_BYTES>>>(hbf, wibf, actbf, win_b);

    // 8) out = act @ wout_w^T + wout_b + xm -> fp32  (BM=64: 384 CTAs)
    tgemm<false, 64><<<dim3(DD/128, ROWS/64), 256, TG_SMEM_BYTES(64)>>>(
        actbf, wobf, out, HID, HID, DD, HID, wout_b, xm);
}